// round 14
// baseline (speedup 1.0000x reference)
#include <cuda_runtime.h>
#include <cuda_bf16.h>
#include <math.h>

typedef unsigned int uint32;

// Problem constants (fixed by setup_inputs)
#define Bv 64
#define Nv 3136
#define Cv 64
#define DOUT 128
#define Wv 56
#define NG 49
#define SAMPLE 784
#define ND 833            // NG + SAMPLE
#define NS 3087           // Nv - NG
#define NSR 196           // (56/4)^2
#define HIDN 512
#define MROWS (Bv*ND)     // 53312
#define MSR   (Bv*NSR)    // 12544
#define KCAT  192         // 128 (oatt) + 64 (xdown)

// ---------------- scratch (static device memory; allocation-free) ----------
__device__ float g_scores[Bv*NS];
__device__ int   g_idx  [Bv*SAMPLE];
__device__ float g_posd [Bv*ND*2];
__device__ float g_segf [Bv*Nv*Cv];
__device__ float g_cnt  [Bv*Nv];
__device__ float g_fmap [Bv*Nv*Cv];
__device__ float g_xs   [MSR*Cv];
__device__ float g_q    [MROWS*DOUT];
__device__ float g_kv   [MSR*256];
__device__ float g_x2   [MROWS*DOUT];
// bf16-split operands for tensor-core GEMMs
__device__ __align__(16) __nv_bfloat16 g_xnh[MROWS*Cv];
__device__ __align__(16) __nv_bfloat16 g_xnl[MROWS*Cv];
__device__ __align__(16) __nv_bfloat16 g_xsh[MSR*Cv];
__device__ __align__(16) __nv_bfloat16 g_xsl[MSR*Cv];
__device__ __align__(16) __nv_bfloat16 g_cath[(size_t)MROWS*KCAT];
__device__ __align__(16) __nv_bfloat16 g_catl[(size_t)MROWS*KCAT];
__device__ __align__(16) __nv_bfloat16 g_xn2h[MROWS*DOUT];
__device__ __align__(16) __nv_bfloat16 g_xn2l[MROWS*DOUT];
__device__ __align__(16) __nv_bfloat16 g_hidh[(size_t)MROWS*HIDN];
__device__ __align__(16) __nv_bfloat16 g_hidl[(size_t)MROWS*HIDN];
__device__ __align__(16) __nv_bfloat16 g_w1h[HIDN*DOUT];   // [n][k]
__device__ __align__(16) __nv_bfloat16 g_w1l[HIDN*DOUT];
__device__ __align__(16) __nv_bfloat16 g_w2h[DOUT*HIDN];
__device__ __align__(16) __nv_bfloat16 g_w2l[DOUT*HIDN];
__device__ __align__(16) __nv_bfloat16 g_wqh[DOUT*Cv];
__device__ __align__(16) __nv_bfloat16 g_wql[DOUT*Cv];
__device__ __align__(16) __nv_bfloat16 g_wkvh[256*Cv];
__device__ __align__(16) __nv_bfloat16 g_wkvl[256*Cv];
__device__ __align__(16) __nv_bfloat16 g_wpfh[DOUT*KCAT];
__device__ __align__(16) __nv_bfloat16 g_wpfl[DOUT*KCAT];
__device__ float g_biaspf[DOUT];

__device__ __forceinline__ float warp_sum(float v){
    #pragma unroll
    for (int o = 16; o; o >>= 1) v = __fadd_rn(v, __shfl_xor_sync(0xffffffffu, v, o));
    return v;
}
__device__ __forceinline__ float warp_max(float v){
    #pragma unroll
    for (int o = 16; o; o >>= 1) v = fmaxf(v, __shfl_xor_sync(0xffffffffu, v, o));
    return v;
}
__device__ __forceinline__ void bsplit(float v, __nv_bfloat16& h, __nv_bfloat16& l){
    h = __float2bfloat16(v);
    l = __float2bfloat16(v - __bfloat162float(h));
}

// ---------------- zero segf/cnt -------------------------------------------
__global__ void zero_kernel(){
    int stride = gridDim.x * blockDim.x;
    int t = blockIdx.x * blockDim.x + threadIdx.x;
    for (int i = t; i < Bv*Nv*Cv; i += stride) g_segf[i] = 0.f;
    for (int i = t; i < Bv*Nv;    i += stride) g_cnt[i]  = 0.f;
}

// ---------------- unified weight prep: transpose+split all weights ---------
__global__ void prep_kernel(const float* __restrict__ fc1_w, const float* __restrict__ fc2_w,
                            const float* __restrict__ q_w, const float* __restrict__ k_w,
                            const float* __restrict__ v_w, const float* __restrict__ proj_w,
                            const float* __restrict__ fc_w,
                            const float* __restrict__ proj_b, const float* __restrict__ fc_b){
    int t = blockIdx.x * blockDim.x + threadIdx.x;
    __nv_bfloat16 h, l;
    if (t < 65536){                      // fc1
        int n = t / DOUT, k = t % DOUT;
        bsplit(fc1_w[(size_t)k*HIDN + n], h, l);
        g_w1h[t] = h; g_w1l[t] = l; return;
    }
    t -= 65536;
    if (t < 65536){                      // fc2
        int n = t / HIDN, k = t % HIDN;
        bsplit(fc2_w[(size_t)k*DOUT + n], h, l);
        g_w2h[t] = h; g_w2l[t] = l; return;
    }
    t -= 65536;
    if (t < 8192){                       // q
        int n = t / Cv, k = t % Cv;
        bsplit(q_w[(size_t)k*DOUT + n], h, l);
        g_wqh[t] = h; g_wql[t] = l; return;
    }
    t -= 8192;
    if (t < 8192){                       // k -> wkv rows [0:128)
        int n = t / Cv, k = t % Cv;
        bsplit(k_w[(size_t)k*DOUT + n], h, l);
        g_wkvh[t] = h; g_wkvl[t] = l; return;
    }
    t -= 8192;
    if (t < 8192){                       // v -> wkv rows [128:256)
        int n = t / Cv, k = t % Cv;
        bsplit(v_w[(size_t)k*DOUT + n], h, l);
        g_wkvh[128*Cv + t] = h; g_wkvl[128*Cv + t] = l; return;
    }
    t -= 8192;
    if (t < 16384){                      // proj -> wpf[n*192+k]
        int n = t / DOUT, k = t % DOUT;
        bsplit(proj_w[(size_t)k*DOUT + n], h, l);
        g_wpfh[(size_t)n*KCAT + k] = h; g_wpfl[(size_t)n*KCAT + k] = l; return;
    }
    t -= 16384;
    if (t < 8192){                       // fc -> wpf[n*192+128+k]
        int n = t / Cv, k = t % Cv;
        bsplit(fc_w[(size_t)k*DOUT + n], h, l);
        g_wpfh[(size_t)n*KCAT + 128 + k] = h; g_wpfl[(size_t)n*KCAT + 128 + k] = l; return;
    }
    t -= 8192;
    if (t < DOUT) g_biaspf[t] = proj_b[t] + fc_b[t];
}

// ------- fused LN+scatter+score: 256 tokens staged in smem per block -------
// Stage x rows coalesced; phase1 warp-per-token LN+scatter (same reduction
// bits as before); phase2 thread-per-token serial score (XLA-CPU semantics).
__global__ void lnscore_kernel(const float* __restrict__ x, const float* __restrict__ pos,
                               const float* __restrict__ noise_u,
                               const float* __restrict__ n1g, const float* __restrict__ n1b,
                               const float* __restrict__ ng, const float* __restrict__ nb,
                               const float* __restrict__ cw, const float* __restrict__ cb){
    extern __shared__ float sx[];            // [256*64] x rows + [512] pos
    float* spos = sx + 256*64;
    int tid = threadIdx.x, lane = tid & 31, w = tid >> 5;
    size_t t0 = (size_t)blockIdx.x * 256;
    const float4* src = (const float4*)(x + t0*64);
    float4* dst = (float4*)sx;
    #pragma unroll
    for (int i = 0; i < 16; i++) dst[tid + i*256] = src[tid + i*256];
    #pragma unroll
    for (int i = 0; i < 2; i++) spos[tid + i*256] = pos[t0*2 + tid + i*256];
    __syncthreads();

    // phase 1: LN + scatter (warp per token, 32 tokens/warp)
    for (int it = 0; it < 32; it++){
        int tk = w*32 + it;
        size_t t = t0 + tk;
        int b = (int)(t / Nv);
        const float* xr = sx + tk*64;
        float v0 = xr[lane], v1 = xr[lane+32];
        float m = warp_sum(v0 + v1) * (1.0f/64.0f);
        float d0 = v0 - m, d1 = v1 - m;
        float var = warp_sum(d0*d0 + d1*d1) * (1.0f/64.0f);
        float rstd = rsqrtf(var + 1e-5f);
        float xsn0 = d0*rstd*n1g[lane]    + n1b[lane];
        float xsn1 = d1*rstd*n1g[lane+32] + n1b[lane+32];
        int p = 0;
        if (lane == 0){
            float px = fminf(fmaxf(spos[tk*2],   0.f), 1.f) * 55.f;
            float py = fminf(fmaxf(spos[tk*2+1], 0.f), 1.f) * 55.f;
            p = (int)rintf(px) + (int)rintf(py) * Wv;   // half-to-even
        }
        p = __shfl_sync(0xffffffffu, p, 0);
        size_t base = ((size_t)b*Nv + p)*64;
        atomicAdd(&g_segf[base + lane],      xsn0);
        atomicAdd(&g_segf[base + lane + 32], xsn1);
        if (lane == 0) atomicAdd(&g_cnt[b*Nv + p], 1.0f);
    }

    // phase 2: score (thread per token, serial XLA-CPU semantics)
    size_t t = t0 + tid;
    int b = (int)(t / Nv), n = (int)(t % Nv);
    if (n >= NG){
        const float* r = sx + tid*64;
        float s = 0.f;
        for (int k = 0; k < 64; k++) s = __fadd_rn(s, r[k]);
        float m = __fdiv_rn(s, 64.0f);
        float vs = 0.f;
        for (int k = 0; k < 64; k++){
            float d = __fsub_rn(r[k], m);
            vs = __fadd_rn(vs, __fmul_rn(d, d));
        }
        float var = __fdiv_rn(vs, 64.0f);
        float rstd = __fdiv_rn(1.0f, sqrtf(__fadd_rn(var, 1e-5f)));  // CPU rsqrt
        float c = 0.f;
        for (int k = 0; k < 64; k++){
            float h = __fmul_rn(__fsub_rn(r[k], m), rstd);
            float tt = __fadd_rn(__fmul_rn(h, ng[k]), nb[k]);
            c = __fadd_rn(c, __fmul_rn(tt, cw[k]));
        }
        float u = noise_u[(size_t)b*NS + (n-NG)];
        float a1 = __fadd_rn(u, 1e-6f);
        float l1 = (float)log((double)a1);
        float inner = __fadd_rn(-l1, 1e-6f);
        float l2 = (float)log((double)inner);
        float noise = -l2;
        g_scores[(size_t)b*NS + (n-NG)] = __fadd_rn(__fadd_rn(c, cb[0]), noise);
    }
}

// ---------------- exact jax top-k: bitonic sort of (score desc, idx asc) ---
__global__ void topk_kernel(){
    __shared__ unsigned long long keys[4096];
    int b = blockIdx.x, tid = threadIdx.x;
    for (int i = tid; i < 4096; i += 1024){
        unsigned long long kk = ~0ULL;
        if (i < NS){
            unsigned u = __float_as_uint(g_scores[(size_t)b*NS + i]);
            u = (u & 0x80000000u) ? ~u : (u | 0x80000000u);
            kk = ((unsigned long long)(~u) << 32) | (unsigned)i;
        }
        keys[i] = kk;
    }
    __syncthreads();
    for (int k = 2; k <= 4096; k <<= 1)
        for (int j = k >> 1; j > 0; j >>= 1){
            for (int t = tid; t < 4096; t += 1024){
                int ixj = t ^ j;
                if (ixj > t){
                    bool up = ((t & k) == 0);
                    unsigned long long a = keys[t], c = keys[ixj];
                    if ((a > c) == up){ keys[t] = c; keys[ixj] = a; }
                }
            }
            __syncthreads();
        }
    for (int i = tid; i < SAMPLE; i += 1024)
        g_idx[b*SAMPLE + i] = (int)(unsigned)(keys[i] & 0xFFFFFFFFULL);
}

// ---- gather: xdown split -> cat cols [128:192), xn split, pos_down --------
__global__ void gather_ln_kernel(const float* __restrict__ x, const float* __restrict__ pos,
                                 const float* __restrict__ n1g, const float* __restrict__ n1b){
    int warp = (blockIdx.x * blockDim.x + threadIdx.x) >> 5;
    int lane = threadIdx.x & 31;
    if (warp >= Bv*ND) return;
    int b = warp / ND, j = warp % ND;
    int n = (j < NG) ? j : (NG + g_idx[b*SAMPLE + (j - NG)]);
    const float* xr = x + ((size_t)b*Nv + n) * Cv;
    float v0 = xr[lane], v1 = xr[lane+32];
    {
        __nv_bfloat16 h, l;
        size_t cb = (size_t)warp*KCAT + 128;
        bsplit(v0, h, l); g_cath[cb + lane]      = h; g_catl[cb + lane]      = l;
        bsplit(v1, h, l); g_cath[cb + lane + 32] = h; g_catl[cb + lane + 32] = l;
    }
    float m = warp_sum(v0 + v1) * (1.0f/64.0f);
    float d0 = v0 - m, d1 = v1 - m;
    float var = warp_sum(d0*d0 + d1*d1) * (1.0f/64.0f);
    float rstd = rsqrtf(var + 1e-5f);
    float xn0 = d0*rstd*n1g[lane]    + n1b[lane];
    float xn1 = d1*rstd*n1g[lane+32] + n1b[lane+32];
    {
        __nv_bfloat16 h, l;
        bsplit(xn0, h, l); g_xnh[(size_t)warp*64 + lane]      = h; g_xnl[(size_t)warp*64 + lane]      = l;
        bsplit(xn1, h, l); g_xnh[(size_t)warp*64 + lane + 32] = h; g_xnl[(size_t)warp*64 + lane + 32] = l;
    }
    if (lane < 2) g_posd[(size_t)warp*2 + lane] = pos[((size_t)b*Nv + n)*2 + lane];
}

// ---------------- normalize + 3x3 gaussian reconstruct fused ----------------
__global__ void blur_kernel(){
    int t = blockIdx.x * blockDim.x + threadIdx.x;
    if (t >= Bv*Nv*Cv) return;
    int c = t & 63; int q = t >> 6; int hw = q % Nv; int b = q / Nv;
    int yy = hw / Wv, xx = hw % Wv;
    const float e1 = 0.88249690f, e2 = 0.77880078f;
    const float S  = 1.0f + 4.0f*(e1 + e2);
    const float wt[3] = {1.0f/S, e1/S, e2/S};
    float cc = g_cnt[b*Nv + hw];
    float maskc = cc > 0.f ? 1.f : 0.f;
    float featc = (g_segf[t] / (cc + 1e-6f)) * maskc;
    float bf = 0.f, bm = 0.f;
    #pragma unroll
    for (int dy = -1; dy <= 1; dy++){
        #pragma unroll
        for (int dx = -1; dx <= 1; dx++){
            int y2 = yy + dy, x2 = xx + dx;
            if (y2 >= 0 && y2 < Wv && x2 >= 0 && x2 < Wv){
                int hw2 = y2*Wv + x2;
                float cn = g_cnt[b*Nv + hw2];
                float mn = cn > 0.f ? 1.f : 0.f;
                float fn = (g_segf[((size_t)b*Nv + hw2)*64 + c] / (cn + 1e-6f)) * mn;
                float w = wt[dy*dy + dx*dx];
                bf += w * fn; bm += w * mn;
            }
        }
    }
    float fi = bf / (bm + 1e-6f);
    fi = (bm > 0.f) ? fi : 0.f;
    g_fmap[t] = featc + (1.f - maskc) * fi;
}

// ---------------- sr 4x4 stride-4 conv as tiled GEMM (fp32) -----------------
__global__ void srconv_kernel(const float* __restrict__ srw, const float* __restrict__ srb){
    __shared__ float As[16][64];
    __shared__ float Bs[16][64];
    int m0 = blockIdx.x * 64;
    int tid = threadIdx.x, tx = tid & 15, ty = tid >> 4;
    float acc[4][4] = {};
    for (int k0 = 0; k0 < 1024; k0 += 16){
        #pragma unroll
        for (int i = 0; i < 4; i++){
            int e = tid + i*256;
            int kk = e & 15, mm = e >> 4;
            int m = m0 + mm, k = k0 + kk;
            int b = m / NSR, s2 = m % NSR;
            int oy = s2 / 14, ox = s2 % 14;
            int kyx = k >> 6, ci = k & 63;
            int ky = kyx >> 2, kx = kyx & 3;
            As[kk][mm] = g_fmap[(((size_t)b*Nv) + (oy*4+ky)*Wv + (ox*4+kx))*64 + ci];
        }
        #pragma unroll
        for (int i = 0; i < 4; i++){
            int e = tid + i*256;
            int n = e & 63, kk = e >> 6;
            int k = k0 + kk;
            int kyx = k >> 6, ci = k & 63;
            Bs[kk][n] = srw[(size_t)n*1024 + ci*16 + kyx];
        }
        __syncthreads();
        #pragma unroll
        for (int kk = 0; kk < 16; kk++){
            float a[4], bb[4];
            #pragma unroll
            for (int i = 0; i < 4; i++) a[i] = As[kk][ty*4+i];
            #pragma unroll
            for (int j = 0; j < 4; j++) bb[j] = Bs[kk][tx*4+j];
            #pragma unroll
            for (int i = 0; i < 4; i++)
                #pragma unroll
                for (int j = 0; j < 4; j++) acc[i][j] += a[i]*bb[j];
        }
        __syncthreads();
    }
    #pragma unroll
    for (int i = 0; i < 4; i++)
        #pragma unroll
        for (int j = 0; j < 4; j++){
            int m = m0 + ty*4 + i, n = tx*4 + j;
            g_xs[(size_t)m*64 + n] = acc[i][j] + srb[n];
        }
}

// ---------------- ln64 -> split bf16 (feeds k/v mma) ------------------------
__global__ void ln64_split_kernel(const float* __restrict__ in,
                                  __nv_bfloat16* __restrict__ oh, __nv_bfloat16* __restrict__ ol,
                                  const float* __restrict__ g, const float* __restrict__ b, int rows){
    int warp = (blockIdx.x * blockDim.x + threadIdx.x) >> 5;
    int lane = threadIdx.x & 31;
    if (warp >= rows) return;
    const float* xr = in + (size_t)warp*64;
    float v0 = xr[lane], v1 = xr[lane+32];
    float m = warp_sum(v0+v1) * (1.0f/64.0f);
    float d0 = v0-m, d1 = v1-m;
    float rstd = rsqrtf(warp_sum(d0*d0+d1*d1)*(1.0f/64.0f) + 1e-5f);
    float o0 = d0*rstd*g[lane]    + b[lane];
    float o1 = d1*rstd*g[lane+32] + b[lane+32];
    __nv_bfloat16 h, l;
    bsplit(o0, h, l); oh[(size_t)warp*64 + lane]      = h; ol[(size_t)warp*64 + lane]      = l;
    bsplit(o1, h, l); oh[(size_t)warp*64 + lane + 32] = h; ol[(size_t)warp*64 + lane + 32] = l;
}

// ---------------- ln128 -> split bf16 (feeds fc1 mma) -----------------------
__global__ void ln128_split_kernel(const float* __restrict__ in,
                                   __nv_bfloat16* __restrict__ oh, __nv_bfloat16* __restrict__ ol,
                                   const float* __restrict__ g, const float* __restrict__ b, int rows){
    int warp = (blockIdx.x * blockDim.x + threadIdx.x) >> 5;
    int lane = threadIdx.x & 31;
    if (warp >= rows) return;
    const float* xr = in + (size_t)warp*128;
    float v[4]; float s = 0.f;
    #pragma unroll
    for (int r = 0; r < 4; r++){ v[r] = xr[lane + 32*r]; s += v[r]; }
    float m = warp_sum(s) * (1.0f/128.0f);
    float vs = 0.f;
    #pragma unroll
    for (int r = 0; r < 4; r++){ v[r] -= m; vs += v[r]*v[r]; }
    float rstd = rsqrtf(warp_sum(vs)*(1.0f/128.0f) + 1e-5f);
    #pragma unroll
    for (int r = 0; r < 4; r++){
        int d = lane + 32*r;
        float o = v[r]*rstd*g[d] + b[d];
        __nv_bfloat16 h, l; bsplit(o, h, l);
        oh[(size_t)warp*128 + d] = h;
        ol[(size_t)warp*128 + d] = l;
    }
}

// ---------------- bf16x3 tensor-core GEMM (mma.sync m16n8k16) ---------------
// smem k-pairs stored permuted: logical pair ac at position ((ac&3)<<1)|(ac>>2),
// row stride 10 words (8B aligned) -> frag gathers become LDS.64.
__device__ __forceinline__ void mma16816(float* c, const uint32* a, const uint32* b){
    asm volatile("mma.sync.aligned.m16n8k16.row.col.f32.bf16.bf16.f32 "
        "{%0,%1,%2,%3}, {%4,%5,%6,%7}, {%8,%9}, {%0,%1,%2,%3};"
        : "+f"(c[0]), "+f"(c[1]), "+f"(c[2]), "+f"(c[3])
        : "r"(a[0]), "r"(a[1]), "r"(a[2]), "r"(a[3]), "r"(b[0]), "r"(b[1]));
}

template<int MODE>
__global__ void mma_gemm_kernel(const __nv_bfloat16* __restrict__ Ah, const __nv_bfloat16* __restrict__ Al,
                                const __nv_bfloat16* __restrict__ Bth, const __nv_bfloat16* __restrict__ Btl,
                                const float* __restrict__ bias, const float* __restrict__ add,
                                float* __restrict__ C,
                                __nv_bfloat16* __restrict__ Oh, __nv_bfloat16* __restrict__ Ol,
                                int M, int N, int K){
    __shared__ __align__(16) uint32 AsH[2][64][10], AsL[2][64][10];
    __shared__ __align__(16) uint32 BsH[2][128][10], BsL[2][128][10];
    int tid = threadIdx.x, lane = tid & 31, wid = tid >> 5;
    int g = lane >> 2, t4 = lane & 3;
    int warp_m = wid >> 1, warp_n = wid & 1;
    int m0 = blockIdx.y * 64, n0 = blockIdx.x * 128;
    int K2 = K >> 1;

    int ar[4], ac[4], ap[4], br[8], bc[8], bp[8];
    #pragma unroll
    for (int i = 0; i < 4; i++){
        int w = tid + i*128; ar[i] = w >> 3; ac[i] = w & 7;
        ap[i] = ((ac[i] & 3) << 1) | (ac[i] >> 2);
    }
    #pragma unroll
    for (int i = 0; i < 8; i++){
        int w = tid + i*128; br[i] = w >> 3; bc[i] = w & 7;
        bp[i] = ((bc[i] & 3) << 1) | (bc[i] >> 2);
    }

    uint32 pah[4], pal[4], pbh[8], pbl[8];
    #pragma unroll
    for (int i = 0; i < 4; i++){
        size_t rowoff = (size_t)(m0 + ar[i]) * K2;
        pah[i] = ((const uint32*)Ah)[rowoff + ac[i]];
        pal[i] = ((const uint32*)Al)[rowoff + ac[i]];
    }
    #pragma unroll
    for (int i = 0; i < 8; i++){
        size_t rowoff = (size_t)(n0 + br[i]) * K2;
        pbh[i] = ((const uint32*)Bth)[rowoff + bc[i]];
        pbl[i] = ((const uint32*)Btl)[rowoff + bc[i]];
    }
    #pragma unroll
    for (int i = 0; i < 4; i++){ AsH[0][ar[i]][ap[i]] = pah[i]; AsL[0][ar[i]][ap[i]] = pal[i]; }
    #pragma unroll
    for (int i = 0; i < 8; i++){ BsH[0][br[i]][bp[i]] = pbh[i]; BsL[0][br[i]][bp[i]] = pbl[i]; }
    __syncthreads();

    float acc[2][8][4];
    #pragma unroll
    for (int fm = 0; fm < 2; fm++)
        #pragma unroll
        for (int fn = 0; fn < 8; fn++)
            #pragma unroll
            for (int i = 0; i < 4; i++) acc[fm][fn][i] = 0.f;

    int nk = K >> 4;
    for (int kt = 0; kt < nk; kt++){
        int cur = kt & 1, nxt = cur ^ 1;
        if (kt + 1 < nk){
            int kw = (kt + 1) * 8;
            #pragma unroll
            for (int i = 0; i < 4; i++){
                size_t rowoff = (size_t)(m0 + ar[i]) * K2 + kw;
                pah[i] = ((const uint32*)Ah)[rowoff + ac[i]];
                pal[i] = ((const uint32*)Al)[rowoff + ac[i]];
            }
            #pragma unroll
            for (int i = 0; i < 8; i++){
                size_t rowoff = (size_t)(n0 + br[i]) * K2 + kw;
                pbh[i] = ((const uint32*)Bth)[rowoff + bc[i]];
                pbl[i] = ((const uint32*)Btl)[rowoff + bc[i]];
            }
        }
        uint32 ah[2][4], al[2][4], bh[8][2], bl[8][2];
        #pragma unroll
        for (int fm = 0; fm < 2; fm++){
            int r0 = warp_m*32 + fm*16 + g;
            uint2 u0 = *(const uint2*)&AsH[cur][r0][2*t4];
            uint2 u1 = *(const uint2*)&AsH[cur][r0+8][2*t4];
            ah[fm][0] = u0.x; ah[fm][1] = u1.x; ah[fm][2] = u0.y; ah[fm][3] = u1.y;
            uint2 v0 = *(const uint2*)&AsL[cur][r0][2*t4];
            uint2 v1 = *(const uint2*)&AsL[cur][r0+8][2*t4];
            al[fm][0] = v0.x; al[fm][1] = v1.x; al[fm][2] = v0.y; al[fm][3] = v1.y;
        }
        #pragma unroll
        for (int fn = 0; fn < 8; fn++){
            int r0 = warp_n*64 + fn*8 + g;
            uint2 u = *(const uint2*)&BsH[cur][r0][2*t4];
            bh[fn][0] = u.x; bh[fn][1] = u.y;
            uint2 v = *(const uint2*)&BsL[cur][r0][2*t4];
            bl[fn][0] = v.x; bl[fn][1] = v.y;
        }
        #pragma unroll
        for (int fn = 0; fn < 8; fn++)
            #pragma unroll
            for (int fm = 0; fm < 2; fm++){
                mma16816(acc[fm][fn], ah[fm], bh[fn]);
                mma16816(acc[fm][fn], ah[fm], bl[fn]);
                mma16816(acc[fm][fn], al[fm], bh[fn]);
            }
        if (kt + 1 < nk){
            #pragma unroll
            for (int i = 0; i < 4; i++){ AsH[nxt][ar[i]][ap[i]] = pah[i]; AsL[nxt][ar[i]][ap[i]] = pal[i]; }
            #pragma unroll
            for (int i = 0; i < 8; i++){ BsH[nxt][br[i]][bp[i]] = pbh[i]; BsL[nxt][br[i]][bp[i]] = pbl[i]; }
            __syncthreads();
        }
    }

    #pragma unroll
    for (int fm = 0; fm < 2; fm++){
        int m1 = m0 + warp_m*32 + fm*16 + g;
        int m2 = m1 + 8;
        #pragma unroll
        for (int fn = 0; fn < 8; fn++){
            int n = n0 + warp_n*64 + fn*8 + t4*2;
            float b0 = bias ? bias[n] : 0.f, b1 = bias ? bias[n+1] : 0.f;
            float c0 = acc[fm][fn][0] + b0;
            float c1 = acc[fm][fn][1] + b1;
            float c2 = acc[fm][fn][2] + b0;
            float c3 = acc[fm][fn][3] + b1;
            if (MODE == 0){
                if (add){
                    c0 += add[(size_t)m1*N + n];   c1 += add[(size_t)m1*N + n + 1];
                    c2 += add[(size_t)m2*N + n];   c3 += add[(size_t)m2*N + n + 1];
                }
                *(float2*)&C[(size_t)m1*N + n] = make_float2(c0, c1);
                *(float2*)&C[(size_t)m2*N + n] = make_float2(c2, c3);
            } else {
                c0 = 0.5f*c0*(1.0f + erff(c0*0.70710678118654752f));
                c1 = 0.5f*c1*(1.0f + erff(c1*0.70710678118654752f));
                c2 = 0.5f*c2*(1.0f + erff(c2*0.70710678118654752f));
                c3 = 0.5f*c3*(1.0f + erff(c3*0.70710678118654752f));
                __nv_bfloat16 h0,l0,h1,l1,h2,l2,h3,l3;
                bsplit(c0,h0,l0); bsplit(c1,h1,l1); bsplit(c2,h2,l2); bsplit(c3,h3,l3);
                __nv_bfloat162 hp1; hp1.x = h0; hp1.y = h1;
                __nv_bfloat162 lp1; lp1.x = l0; lp1.y = l1;
                __nv_bfloat162 hp2; hp2.x = h2; hp2.y = h3;
                __nv_bfloat162 lp2; lp2.x = l2; lp2.y = l3;
                *(__nv_bfloat162*)&Oh[(size_t)m1*N + n] = hp1;
                *(__nv_bfloat162*)&Ol[(size_t)m1*N + n] = lp1;
                *(__nv_bfloat162*)&Oh[(size_t)m2*N + n] = hp2;
                *(__nv_bfloat162*)&Ol[(size_t)m2*N + n] = lp2;
            }
        }
    }
}

// ---------------- fused cross-attention (512 threads, 4 q per warp) ---------
#define QPW 4
#define JPAD 224
__global__ void attn_kernel(){
    extern __shared__ float sm[];
    float* Ks = sm;                          // [224][65]
    float* Vs = Ks + JPAD*65;                // [224][64]
    float* Qs = Vs + JPAD*64;                // [64][64]
    float* Pp = Qs + 64*64;                  // [64][196]
    int bh = blockIdx.y;
    int b = bh >> 1, h = bh & 1;
    int tid = threadIdx.x, lane = tid & 31, w = tid >> 5;
    for (int e = tid; e < JPAD*64; e += 512){
        int j = e >> 6, d = e & 63;
        float kv = 0.f, vv = 0.f;
        if (j < NSR){
            size_t base = ((size_t)b*NSR + j)*256 + h*64 + d;
            kv = g_kv[base]; vv = g_kv[base + 128];
        }
        Ks[j*65 + d] = kv;
        Vs[e] = vv;
    }
    int qbase = blockIdx.x * 64 + w * QPW;
    for (int e = lane; e < QPW*64; e += 32){
        int qi = e >> 6, d = e & 63;
        int gq = qbase + qi;
        Qs[(w*QPW + qi)*64 + d] = (gq < ND) ? g_q[((size_t)b*ND + gq)*128 + h*64 + d] : 0.f;
    }
    __syncthreads();

    float acc[QPW][7];
    #pragma unroll
    for (int qi = 0; qi < QPW; qi++)
        #pragma unroll
        for (int t = 0; t < 7; t++) acc[qi][t] = 0.f;

    for (int d = 0; d < 64; d++){
        float qv[QPW];
        #pragma unroll
        for (int qi = 0; qi < QPW; qi++) qv[qi] = Qs[(w*QPW + qi)*64 + d];
        #pragma unroll
        for (int t = 0; t < 7; t++){
            float kv = Ks[(lane + 32*t)*65 + d];
            #pragma unroll
            for (int qi = 0; qi < QPW; qi++) acc[qi][t] += qv[qi]*kv;
        }
    }
    const float scale = 0.17677669529663687f;
    float sums[QPW];
    #pragma unroll
    for (int qi = 0; qi < QPW; qi++){
        float mx = -1e30f;
        #pragma unroll
        for (int t = 0; t < 7; t++){
            int j = lane + 32*t;
            acc[qi][t] *= scale;
            if (j < NSR) mx = fmaxf(mx, acc[qi][t]);
        }
        mx = warp_max(mx);
        float s = 0.f;
        #pragma unroll
        for (int t = 0; t < 7; t++){
            int j = lane + 32*t;
            if (j < NSR){
                float e = expf(acc[qi][t] - mx);
                Pp[(w*QPW + qi)*196 + j] = e;
                s += e;
            }
        }
        sums[qi] = warp_sum(s);
    }
    __syncwarp();
    float o0[QPW] = {}, o1[QPW] = {};
    for (int j = 0; j < NSR; j++){
        float v0 = Vs[j*64 + lane], v1 = Vs[j*64 + lane + 32];
        #pragma unroll
        for (int qi = 0; qi < QPW; qi++){
            float p = Pp[(w*QPW + qi)*196 + j];
            o0[qi] += p*v0; o1[qi] += p*v1;
        }
    }
    #pragma unroll
    for (int qi = 0; qi < QPW; qi++){
        int gq = qbase + qi;
        if (gq < ND){
            size_t cb = ((size_t)b*ND + gq)*KCAT + h*64;
            float inv = 1.0f / sums[qi];
            __nv_bfloat16 hh, ll;
            bsplit(o0[qi]*inv, hh, ll); g_cath[cb + lane]      = hh; g_catl[cb + lane]      = ll;
            bsplit(o1[qi]*inv, hh, ll); g_cath[cb + lane + 32] = hh; g_catl[cb + lane + 32] = ll;
        }
    }
}

// ---------------- bilinear grid-sample of pos_embed, add into out -----------
__global__ void possample_kernel(const float* __restrict__ pe, float* __restrict__ out){
    int warp = (blockIdx.x * blockDim.x + threadIdx.x) >> 5;
    int lane = threadIdx.x & 31;
    if (warp >= Bv*ND) return;
    float px = g_posd[(size_t)warp*2], py = g_posd[(size_t)warp*2 + 1];
    float gx = px*2.f - 1.f, gy = py*2.f - 1.f;
    float ix = ((gx + 1.f)*56.f - 1.f)*0.5f;
    float iy = ((gy + 1.f)*56.f - 1.f)*0.5f;
    float x0 = floorf(ix), y0 = floorf(iy);
    float wx = ix - x0,   wy = iy - y0;
    float accv[4] = {};
    #pragma unroll
    for (int cy = 0; cy < 2; cy++){
        #pragma unroll
        for (int cx = 0; cx < 2; cx++){
            float xc = x0 + cx, yc = y0 + cy;
            float wgt = (cx ? wx : 1.f-wx) * (cy ? wy : 1.f-wy);
            bool valid = (xc >= 0.f) && (xc < 56.f) && (yc >= 0.f) && (yc < 56.f);
            float wv = valid ? wgt : 0.f;
            int xi = (int)fminf(fmaxf(xc, 0.f), 55.f);
            int yi = (int)fminf(fmaxf(yc, 0.f), 55.f);
            int lin = yi*56 + xi;
            #pragma unroll
            for (int r = 0; r < 4; r++)
                accv[r] += pe[(size_t)lin*128 + lane + 32*r] * wv;
        }
    }
    #pragma unroll
    for (int r = 0; r < 4; r++)
        out[(size_t)warp*128 + lane + 32*r] += accv[r];
}

// ---------------- launcher ---------------------------------------------------
extern "C" void kernel_launch(void* const* d_in, const int* in_sizes, int n_in,
                              void* d_out, int out_size){
    const float* x        = (const float*)d_in[0];
    const float* pos      = (const float*)d_in[1];
    const float* pos_embed= (const float*)d_in[2];
    const float* noise_u  = (const float*)d_in[3];
    const float* norm_g   = (const float*)d_in[4];
    const float* norm_b   = (const float*)d_in[5];
    const float* conf_w   = (const float*)d_in[6];
    const float* conf_b   = (const float*)d_in[7];
    const float* n1g      = (const float*)d_in[8];
    const float* n1b      = (const float*)d_in[9];
    const float* q_w      = (const float*)d_in[10];
    const float* k_w      = (const float*)d_in[11];
    const float* v_w      = (const float*)d_in[12];
    const float* proj_w   = (const float*)d_in[13];
    const float* proj_b   = (const float*)d_in[14];
    const float* sr_w     = (const float*)d_in[15];
    const float* sr_b     = (const float*)d_in[16];
    const float* srn_g    = (const float*)d_in[17];
    const float* srn_b    = (const float*)d_in[18];
    const float* fc_w     = (const float*)d_in[19];
    const float* fc_b     = (const float*)d_in[20];
    const float* n2g      = (const float*)d_in[21];
    const float* n2b      = (const float*)d_in[22];
    const float* fc1_w    = (const float*)d_in[23];
    const float* fc1_b    = (const float*)d_in[24];
    const float* fc2_w    = (const float*)d_in[25];
    const float* fc2_b    = (const float*)d_in[26];
    float* out = (float*)d_out;

    float *p_xs, *p_q, *p_kv, *p_x2, *p_biaspf;
    __nv_bfloat16 *p_xnh, *p_xnl, *p_xsh, *p_xsl, *p_cath, *p_catl;
    __nv_bfloat16 *p_xn2h, *p_xn2l, *p_hidh, *p_hidl;
    __nv_bfloat16 *p_w1h, *p_w1l, *p_w2h, *p_w2l, *p_wqh, *p_wql, *p_wkvh, *p_wkvl, *p_wpfh, *p_wpfl;
    cudaGetSymbolAddress((void**)&p_xs,    g_xs);
    cudaGetSymbolAddress((void**)&p_q,     g_q);
    cudaGetSymbolAddress((void**)&p_kv,    g_kv);
    cudaGetSymbolAddress((void**)&p_x2,    g_x2);
    cudaGetSymbolAddress((void**)&p_biaspf,g_biaspf);
    cudaGetSymbolAddress((void**)&p_xnh,   g_xnh);
    cudaGetSymbolAddress((void**)&p_xnl,   g_xnl);
    cudaGetSymbolAddress((void**)&p_xsh,   g_xsh);
    cudaGetSymbolAddress((void**)&p_xsl,   g_xsl);
    cudaGetSymbolAddress((void**)&p_cath,  g_cath);
    cudaGetSymbolAddress((void**)&p_catl,  g_catl);
    cudaGetSymbolAddress((void**)&p_xn2h,  g_xn2h);
    cudaGetSymbolAddress((void**)&p_xn2l,  g_xn2l);
    cudaGetSymbolAddress((void**)&p_hidh,  g_hidh);
    cudaGetSymbolAddress((void**)&p_hidl,  g_hidl);
    cudaGetSymbolAddress((void**)&p_w1h,   g_w1h);
    cudaGetSymbolAddress((void**)&p_w1l,   g_w1l);
    cudaGetSymbolAddress((void**)&p_w2h,   g_w2h);
    cudaGetSymbolAddress((void**)&p_w2l,   g_w2l);
    cudaGetSymbolAddress((void**)&p_wqh,   g_wqh);
    cudaGetSymbolAddress((void**)&p_wql,   g_wql);
    cudaGetSymbolAddress((void**)&p_wkvh,  g_wkvh);
    cudaGetSymbolAddress((void**)&p_wkvl,  g_wkvl);
    cudaGetSymbolAddress((void**)&p_wpfh,  g_wpfh);
    cudaGetSymbolAddress((void**)&p_wpfl,  g_wpfl);

    zero_kernel<<<4096, 256>>>();
    prep_kernel<<<(180288 + 255)/256, 256>>>(fc1_w, fc2_w, q_w, k_w, v_w, proj_w, fc_w, proj_b, fc_b);

    // fused LN+scatter+score (coalesced smem staging)
    size_t ls_smem = (256*64 + 512) * sizeof(float);
    cudaFuncSetAttribute(lnscore_kernel, cudaFuncAttributeMaxDynamicSharedMemorySize, (int)ls_smem);
    lnscore_kernel<<<Bv*Nv/256, 256, ls_smem>>>(x, pos, noise_u, n1g, n1b, norm_g, norm_b, conf_w, conf_b);

    topk_kernel<<<Bv, 1024>>>();
    gather_ln_kernel<<<(Bv*ND + 7)/8, 256>>>(x, pos, n1g, n1b);
    blur_kernel<<<(Bv*Nv*Cv + 255)/256, 256>>>();
    srconv_kernel<<<196, 256>>>(sr_w, sr_b);
    ln64_split_kernel<<<(MSR + 7)/8, 256>>>(p_xs, p_xsh, p_xsl, srn_g, srn_b, MSR);

    // q = xn @ q_w ; [k|v] = xs @ [k_w|v_w]   (tensor cores, no bias)
    mma_gemm_kernel<0><<<dim3(1, MROWS/64), 128>>>(
        p_xnh, p_xnl, p_wqh, p_wql, nullptr, nullptr, p_q, nullptr, nullptr, MROWS, 128, 64);
    mma_gemm_kernel<0><<<dim3(2, MSR/64), 128>>>(
        p_xsh, p_xsl, p_wkvh, p_wkvl, nullptr, nullptr, p_kv, nullptr, nullptr, MSR, 256, 64);

    // fused attention -> concat buffer cols [0:128)
    size_t attn_smem = (size_t)(JPAD*65 + JPAD*64 + 64*64 + 64*196) * sizeof(float);
    cudaFuncSetAttribute(attn_kernel, cudaFuncAttributeMaxDynamicSharedMemorySize, (int)attn_smem);
    attn_kernel<<<dim3(14, Bv*2), 512, attn_smem>>>();

    // x2 = [oatt|xdown] @ [proj_w;fc_w] + (proj_b+fc_b)   (K=192)
    mma_gemm_kernel<0><<<dim3(1, MROWS/64), 128>>>(
        p_cath, p_catl, p_wpfh, p_wpfl, p_biaspf, nullptr, p_x2, nullptr, nullptr, MROWS, 128, KCAT);

    // LN2 -> split bf16 xn2
    ln128_split_kernel<<<(Bv*ND + 7)/8, 256>>>(p_x2, p_xn2h, p_xn2l, n2g, n2b, Bv*ND);

    // hid = gelu(xn2 @ fc1 + b1) -> split bf16 (tensor cores)
    mma_gemm_kernel<1><<<dim3(HIDN/128, MROWS/64), 128>>>(
        p_xn2h, p_xn2l, p_w1h, p_w1l, fc1_b, nullptr, nullptr, p_hidh, p_hidl,
        MROWS, HIDN, DOUT);
    // out = x2 + hid @ fc2 + b2 (tensor cores)
    mma_gemm_kernel<0><<<dim3(DOUT/128, MROWS/64), 128>>>(
        p_hidh, p_hidl, p_w2h, p_w2l, fc2_b, p_x2, out, nullptr, nullptr,
        MROWS, DOUT, HIDN);

    // out += grid_sample(pos_embed)
    possample_kernel<<<(Bv*ND + 7)/8, 256>>>(pos_embed, out);
}

// round 15
// speedup vs baseline: 1.0995x; 1.0995x over previous
#include <cuda_runtime.h>
#include <cuda_bf16.h>
#include <math.h>

typedef unsigned int uint32;

// Problem constants (fixed by setup_inputs)
#define Bv 64
#define Nv 3136
#define Cv 64
#define DOUT 128
#define Wv 56
#define NG 49
#define SAMPLE 784
#define ND 833            // NG + SAMPLE
#define NS 3087           // Nv - NG
#define NSR 196           // (56/4)^2
#define HIDN 512
#define MROWS (Bv*ND)     // 53312
#define MSR   (Bv*NSR)    // 12544
#define KCAT  192         // 128 (oatt) + 64 (xdown)

// ---------------- scratch (static device memory; allocation-free) ----------
__device__ float g_scores[Bv*NS];
__device__ int   g_idx  [Bv*SAMPLE];
__device__ float g_posd [Bv*ND*2];
__device__ float g_segf [Bv*Nv*Cv];
__device__ float g_cnt  [Bv*Nv];
__device__ float g_fmap [Bv*Nv*Cv];
__device__ float g_xs   [MSR*Cv];
__device__ float g_x2   [MROWS*DOUT];
// bf16-split operands for tensor-core GEMMs
__device__ __align__(16) __nv_bfloat16 g_xnh[MROWS*Cv];
__device__ __align__(16) __nv_bfloat16 g_xnl[MROWS*Cv];
__device__ __align__(16) __nv_bfloat16 g_xsh[MSR*Cv];
__device__ __align__(16) __nv_bfloat16 g_xsl[MSR*Cv];
__device__ __align__(16) __nv_bfloat16 g_qh [MROWS*DOUT];
__device__ __align__(16) __nv_bfloat16 g_ql [MROWS*DOUT];
__device__ __align__(16) __nv_bfloat16 g_kvh[MSR*256];
__device__ __align__(16) __nv_bfloat16 g_kvl[MSR*256];
__device__ __align__(16) __nv_bfloat16 g_cath[(size_t)MROWS*KCAT];
__device__ __align__(16) __nv_bfloat16 g_catl[(size_t)MROWS*KCAT];
__device__ __align__(16) __nv_bfloat16 g_xn2h[MROWS*DOUT];
__device__ __align__(16) __nv_bfloat16 g_xn2l[MROWS*DOUT];
__device__ __align__(16) __nv_bfloat16 g_hidh[(size_t)MROWS*HIDN];
__device__ __align__(16) __nv_bfloat16 g_hidl[(size_t)MROWS*HIDN];
__device__ __align__(16) __nv_bfloat16 g_w1h[HIDN*DOUT];   // [n][k]
__device__ __align__(16) __nv_bfloat16 g_w1l[HIDN*DOUT];
__device__ __align__(16) __nv_bfloat16 g_w2h[DOUT*HIDN];
__device__ __align__(16) __nv_bfloat16 g_w2l[DOUT*HIDN];
__device__ __align__(16) __nv_bfloat16 g_wqh[DOUT*Cv];
__device__ __align__(16) __nv_bfloat16 g_wql[DOUT*Cv];
__device__ __align__(16) __nv_bfloat16 g_wkvh[256*Cv];
__device__ __align__(16) __nv_bfloat16 g_wkvl[256*Cv];
__device__ __align__(16) __nv_bfloat16 g_wpfh[DOUT*KCAT];
__device__ __align__(16) __nv_bfloat16 g_wpfl[DOUT*KCAT];
__device__ float g_biaspf[DOUT];

__device__ __forceinline__ float warp_sum(float v){
    #pragma unroll
    for (int o = 16; o; o >>= 1) v = __fadd_rn(v, __shfl_xor_sync(0xffffffffu, v, o));
    return v;
}
__device__ __forceinline__ void bsplit(float v, __nv_bfloat16& h, __nv_bfloat16& l){
    h = __float2bfloat16(v);
    l = __float2bfloat16(v - __bfloat162float(h));
}
__device__ __forceinline__ void pack2_split(float a, float b, uint32& hi, uint32& lo){
    __nv_bfloat16 ha, la, hb, lb;
    bsplit(a, ha, la); bsplit(b, hb, lb);
    __nv_bfloat162 ph; ph.x = ha; ph.y = hb;
    __nv_bfloat162 pl; pl.x = la; pl.y = lb;
    hi = *(uint32*)&ph; lo = *(uint32*)&pl;
}

// ---------------- zero segf/cnt -------------------------------------------
__global__ void zero_kernel(){
    int stride = gridDim.x * blockDim.x;
    int t = blockIdx.x * blockDim.x + threadIdx.x;
    for (int i = t; i < Bv*Nv*Cv; i += stride) g_segf[i] = 0.f;
    for (int i = t; i < Bv*Nv;    i += stride) g_cnt[i]  = 0.f;
}

// ---------------- unified weight prep: transpose+split all weights ---------
__global__ void prep_kernel(const float* __restrict__ fc1_w, const float* __restrict__ fc2_w,
                            const float* __restrict__ q_w, const float* __restrict__ k_w,
                            const float* __restrict__ v_w, const float* __restrict__ proj_w,
                            const float* __restrict__ fc_w,
                            const float* __restrict__ proj_b, const float* __restrict__ fc_b){
    int t = blockIdx.x * blockDim.x + threadIdx.x;
    __nv_bfloat16 h, l;
    if (t < 65536){                      // fc1
        int n = t / DOUT, k = t % DOUT;
        bsplit(fc1_w[(size_t)k*HIDN + n], h, l);
        g_w1h[t] = h; g_w1l[t] = l; return;
    }
    t -= 65536;
    if (t < 65536){                      // fc2
        int n = t / HIDN, k = t % HIDN;
        bsplit(fc2_w[(size_t)k*DOUT + n], h, l);
        g_w2h[t] = h; g_w2l[t] = l; return;
    }
    t -= 65536;
    if (t < 8192){                       // q
        int n = t / Cv, k = t % Cv;
        bsplit(q_w[(size_t)k*DOUT + n], h, l);
        g_wqh[t] = h; g_wql[t] = l; return;
    }
    t -= 8192;
    if (t < 8192){                       // k -> wkv rows [0:128)
        int n = t / Cv, k = t % Cv;
        bsplit(k_w[(size_t)k*DOUT + n], h, l);
        g_wkvh[t] = h; g_wkvl[t] = l; return;
    }
    t -= 8192;
    if (t < 8192){                       // v -> wkv rows [128:256)
        int n = t / Cv, k = t % Cv;
        bsplit(v_w[(size_t)k*DOUT + n], h, l);
        g_wkvh[128*Cv + t] = h; g_wkvl[128*Cv + t] = l; return;
    }
    t -= 8192;
    if (t < 16384){                      // proj -> wpf[n*192+k]
        int n = t / DOUT, k = t % DOUT;
        bsplit(proj_w[(size_t)k*DOUT + n], h, l);
        g_wpfh[(size_t)n*KCAT + k] = h; g_wpfl[(size_t)n*KCAT + k] = l; return;
    }
    t -= 16384;
    if (t < 8192){                       // fc -> wpf[n*192+128+k]
        int n = t / Cv, k = t % Cv;
        bsplit(fc_w[(size_t)k*DOUT + n], h, l);
        g_wpfh[(size_t)n*KCAT + 128 + k] = h; g_wpfl[(size_t)n*KCAT + 128 + k] = l; return;
    }
    t -= 8192;
    if (t < DOUT) g_biaspf[t] = proj_b[t] + fc_b[t];
}

// ------- fused LN+scatter+score: 256 tokens staged in smem per block -------
__global__ void lnscore_kernel(const float* __restrict__ x, const float* __restrict__ pos,
                               const float* __restrict__ noise_u,
                               const float* __restrict__ n1g, const float* __restrict__ n1b,
                               const float* __restrict__ ng, const float* __restrict__ nb,
                               const float* __restrict__ cw, const float* __restrict__ cb){
    extern __shared__ float sx[];            // [256*64] x rows + [512] pos
    float* spos = sx + 256*64;
    int tid = threadIdx.x, lane = tid & 31, w = tid >> 5;
    size_t t0 = (size_t)blockIdx.x * 256;
    const float4* src = (const float4*)(x + t0*64);
    float4* dst = (float4*)sx;
    #pragma unroll
    for (int i = 0; i < 16; i++) dst[tid + i*256] = src[tid + i*256];
    #pragma unroll
    for (int i = 0; i < 2; i++) spos[tid + i*256] = pos[t0*2 + tid + i*256];
    __syncthreads();

    // phase 1: LN + scatter (warp per token, 32 tokens/warp)
    for (int it = 0; it < 32; it++){
        int tk = w*32 + it;
        size_t t = t0 + tk;
        int b = (int)(t / Nv);
        const float* xr = sx + tk*64;
        float v0 = xr[lane], v1 = xr[lane+32];
        float m = warp_sum(v0 + v1) * (1.0f/64.0f);
        float d0 = v0 - m, d1 = v1 - m;
        float var = warp_sum(d0*d0 + d1*d1) * (1.0f/64.0f);
        float rstd = rsqrtf(var + 1e-5f);
        float xsn0 = d0*rstd*n1g[lane]    + n1b[lane];
        float xsn1 = d1*rstd*n1g[lane+32] + n1b[lane+32];
        int p = 0;
        if (lane == 0){
            float px = fminf(fmaxf(spos[tk*2],   0.f), 1.f) * 55.f;
            float py = fminf(fmaxf(spos[tk*2+1], 0.f), 1.f) * 55.f;
            p = (int)rintf(px) + (int)rintf(py) * Wv;   // half-to-even
        }
        p = __shfl_sync(0xffffffffu, p, 0);
        size_t base = ((size_t)b*Nv + p)*64;
        atomicAdd(&g_segf[base + lane],      xsn0);
        atomicAdd(&g_segf[base + lane + 32], xsn1);
        if (lane == 0) atomicAdd(&g_cnt[b*Nv + p], 1.0f);
    }

    // phase 2: score (thread per token, serial XLA-CPU semantics)
    size_t t = t0 + tid;
    int b = (int)(t / Nv), n = (int)(t % Nv);
    if (n >= NG){
        const float* r = sx + tid*64;
        float s = 0.f;
        for (int k = 0; k < 64; k++) s = __fadd_rn(s, r[k]);
        float m = __fdiv_rn(s, 64.0f);
        float vs = 0.f;
        for (int k = 0; k < 64; k++){
            float d = __fsub_rn(r[k], m);
            vs = __fadd_rn(vs, __fmul_rn(d, d));
        }
        float var = __fdiv_rn(vs, 64.0f);
        float rstd = __fdiv_rn(1.0f, sqrtf(__fadd_rn(var, 1e-5f)));  // CPU rsqrt
        float c = 0.f;
        for (int k = 0; k < 64; k++){
            float h = __fmul_rn(__fsub_rn(r[k], m), rstd);
            float tt = __fadd_rn(__fmul_rn(h, ng[k]), nb[k]);
            c = __fadd_rn(c, __fmul_rn(tt, cw[k]));
        }
        float u = noise_u[(size_t)b*NS + (n-NG)];
        float a1 = __fadd_rn(u, 1e-6f);
        float l1 = (float)log((double)a1);
        float inner = __fadd_rn(-l1, 1e-6f);
        float l2 = (float)log((double)inner);
        float noise = -l2;
        g_scores[(size_t)b*NS + (n-NG)] = __fadd_rn(__fadd_rn(c, cb[0]), noise);
    }
}

// ---------------- exact jax top-k: bitonic sort of (score desc, idx asc) ---
__global__ void topk_kernel(){
    __shared__ unsigned long long keys[4096];
    int b = blockIdx.x, tid = threadIdx.x;
    for (int i = tid; i < 4096; i += 1024){
        unsigned long long kk = ~0ULL;
        if (i < NS){
            unsigned u = __float_as_uint(g_scores[(size_t)b*NS + i]);
            u = (u & 0x80000000u) ? ~u : (u | 0x80000000u);
            kk = ((unsigned long long)(~u) << 32) | (unsigned)i;
        }
        keys[i] = kk;
    }
    __syncthreads();
    for (int k = 2; k <= 4096; k <<= 1)
        for (int j = k >> 1; j > 0; j >>= 1){
            for (int t = tid; t < 4096; t += 1024){
                int ixj = t ^ j;
                if (ixj > t){
                    bool up = ((t & k) == 0);
                    unsigned long long a = keys[t], c = keys[ixj];
                    if ((a > c) == up){ keys[t] = c; keys[ixj] = a; }
                }
            }
            __syncthreads();
        }
    for (int i = tid; i < SAMPLE; i += 1024)
        g_idx[b*SAMPLE + i] = (int)(unsigned)(keys[i] & 0xFFFFFFFFULL);
}

// ---- gather: xdown split -> cat cols [128:192), xn split, pos_down --------
__global__ void gather_ln_kernel(const float* __restrict__ x, const float* __restrict__ pos,
                                 const float* __restrict__ n1g, const float* __restrict__ n1b){
    int warp = (blockIdx.x * blockDim.x + threadIdx.x) >> 5;
    int lane = threadIdx.x & 31;
    if (warp >= Bv*ND) return;
    int b = warp / ND, j = warp % ND;
    int n = (j < NG) ? j : (NG + g_idx[b*SAMPLE + (j - NG)]);
    const float* xr = x + ((size_t)b*Nv + n) * Cv;
    float v0 = xr[lane], v1 = xr[lane+32];
    {
        __nv_bfloat16 h, l;
        size_t cb = (size_t)warp*KCAT + 128;
        bsplit(v0, h, l); g_cath[cb + lane]      = h; g_catl[cb + lane]      = l;
        bsplit(v1, h, l); g_cath[cb + lane + 32] = h; g_catl[cb + lane + 32] = l;
    }
    float m = warp_sum(v0 + v1) * (1.0f/64.0f);
    float d0 = v0 - m, d1 = v1 - m;
    float var = warp_sum(d0*d0 + d1*d1) * (1.0f/64.0f);
    float rstd = rsqrtf(var + 1e-5f);
    float xn0 = d0*rstd*n1g[lane]    + n1b[lane];
    float xn1 = d1*rstd*n1g[lane+32] + n1b[lane+32];
    {
        __nv_bfloat16 h, l;
        bsplit(xn0, h, l); g_xnh[(size_t)warp*64 + lane]      = h; g_xnl[(size_t)warp*64 + lane]      = l;
        bsplit(xn1, h, l); g_xnh[(size_t)warp*64 + lane + 32] = h; g_xnl[(size_t)warp*64 + lane + 32] = l;
    }
    if (lane < 2) g_posd[(size_t)warp*2 + lane] = pos[((size_t)b*Nv + n)*2 + lane];
}

// ---------------- normalize + 3x3 gaussian reconstruct fused ----------------
__global__ void blur_kernel(){
    int t = blockIdx.x * blockDim.x + threadIdx.x;
    if (t >= Bv*Nv*Cv) return;
    int c = t & 63; int q = t >> 6; int hw = q % Nv; int b = q / Nv;
    int yy = hw / Wv, xx = hw % Wv;
    const float e1 = 0.88249690f, e2 = 0.77880078f;
    const float S  = 1.0f + 4.0f*(e1 + e2);
    const float wt[3] = {1.0f/S, e1/S, e2/S};
    float cc = g_cnt[b*Nv + hw];
    float maskc = cc > 0.f ? 1.f : 0.f;
    float featc = (g_segf[t] / (cc + 1e-6f)) * maskc;
    float bf = 0.f, bm = 0.f;
    #pragma unroll
    for (int dy = -1; dy <= 1; dy++){
        #pragma unroll
        for (int dx = -1; dx <= 1; dx++){
            int y2 = yy + dy, x2 = xx + dx;
            if (y2 >= 0 && y2 < Wv && x2 >= 0 && x2 < Wv){
                int hw2 = y2*Wv + x2;
                float cn = g_cnt[b*Nv + hw2];
                float mn = cn > 0.f ? 1.f : 0.f;
                float fn = (g_segf[((size_t)b*Nv + hw2)*64 + c] / (cn + 1e-6f)) * mn;
                float w = wt[dy*dy + dx*dx];
                bf += w * fn; bm += w * mn;
            }
        }
    }
    float fi = bf / (bm + 1e-6f);
    fi = (bm > 0.f) ? fi : 0.f;
    g_fmap[t] = featc + (1.f - maskc) * fi;
}

// ---------------- sr 4x4 stride-4 conv as tiled GEMM (fp32) -----------------
__global__ void srconv_kernel(const float* __restrict__ srw, const float* __restrict__ srb){
    __shared__ float As[16][64];
    __shared__ float Bs[16][64];
    int m0 = blockIdx.x * 64;
    int tid = threadIdx.x, tx = tid & 15, ty = tid >> 4;
    float acc[4][4] = {};
    for (int k0 = 0; k0 < 1024; k0 += 16){
        #pragma unroll
        for (int i = 0; i < 4; i++){
            int e = tid + i*256;
            int kk = e & 15, mm = e >> 4;
            int m = m0 + mm, k = k0 + kk;
            int b = m / NSR, s2 = m % NSR;
            int oy = s2 / 14, ox = s2 % 14;
            int kyx = k >> 6, ci = k & 63;
            int ky = kyx >> 2, kx = kyx & 3;
            As[kk][mm] = g_fmap[(((size_t)b*Nv) + (oy*4+ky)*Wv + (ox*4+kx))*64 + ci];
        }
        #pragma unroll
        for (int i = 0; i < 4; i++){
            int e = tid + i*256;
            int n = e & 63, kk = e >> 6;
            int k = k0 + kk;
            int kyx = k >> 6, ci = k & 63;
            Bs[kk][n] = srw[(size_t)n*1024 + ci*16 + kyx];
        }
        __syncthreads();
        #pragma unroll
        for (int kk = 0; kk < 16; kk++){
            float a[4], bb[4];
            #pragma unroll
            for (int i = 0; i < 4; i++) a[i] = As[kk][ty*4+i];
            #pragma unroll
            for (int j = 0; j < 4; j++) bb[j] = Bs[kk][tx*4+j];
            #pragma unroll
            for (int i = 0; i < 4; i++)
                #pragma unroll
                for (int j = 0; j < 4; j++) acc[i][j] += a[i]*bb[j];
        }
        __syncthreads();
    }
    #pragma unroll
    for (int i = 0; i < 4; i++)
        #pragma unroll
        for (int j = 0; j < 4; j++){
            int m = m0 + ty*4 + i, n = tx*4 + j;
            g_xs[(size_t)m*64 + n] = acc[i][j] + srb[n];
        }
}

// ---------------- ln64 -> split bf16 (feeds k/v mma) ------------------------
__global__ void ln64_split_kernel(const float* __restrict__ in,
                                  __nv_bfloat16* __restrict__ oh, __nv_bfloat16* __restrict__ ol,
                                  const float* __restrict__ g, const float* __restrict__ b, int rows){
    int warp = (blockIdx.x * blockDim.x + threadIdx.x) >> 5;
    int lane = threadIdx.x & 31;
    if (warp >= rows) return;
    const float* xr = in + (size_t)warp*64;
    float v0 = xr[lane], v1 = xr[lane+32];
    float m = warp_sum(v0+v1) * (1.0f/64.0f);
    float d0 = v0-m, d1 = v1-m;
    float rstd = rsqrtf(warp_sum(d0*d0+d1*d1)*(1.0f/64.0f) + 1e-5f);
    float o0 = d0*rstd*g[lane]    + b[lane];
    float o1 = d1*rstd*g[lane+32] + b[lane+32];
    __nv_bfloat16 h, l;
    bsplit(o0, h, l); oh[(size_t)warp*64 + lane]      = h; ol[(size_t)warp*64 + lane]      = l;
    bsplit(o1, h, l); oh[(size_t)warp*64 + lane + 32] = h; ol[(size_t)warp*64 + lane + 32] = l;
}

// ---------------- ln128 -> split bf16 (feeds fc1 mma) -----------------------
__global__ void ln128_split_kernel(const float* __restrict__ in,
                                   __nv_bfloat16* __restrict__ oh, __nv_bfloat16* __restrict__ ol,
                                   const float* __restrict__ g, const float* __restrict__ b, int rows){
    int warp = (blockIdx.x * blockDim.x + threadIdx.x) >> 5;
    int lane = threadIdx.x & 31;
    if (warp >= rows) return;
    const float* xr = in + (size_t)warp*128;
    float v[4]; float s = 0.f;
    #pragma unroll
    for (int r = 0; r < 4; r++){ v[r] = xr[lane + 32*r]; s += v[r]; }
    float m = warp_sum(s) * (1.0f/128.0f);
    float vs = 0.f;
    #pragma unroll
    for (int r = 0; r < 4; r++){ v[r] -= m; vs += v[r]*v[r]; }
    float rstd = rsqrtf(warp_sum(vs)*(1.0f/128.0f) + 1e-5f);
    #pragma unroll
    for (int r = 0; r < 4; r++){
        int d = lane + 32*r;
        float o = v[r]*rstd*g[d] + b[d];
        __nv_bfloat16 h, l; bsplit(o, h, l);
        oh[(size_t)warp*128 + d] = h;
        ol[(size_t)warp*128 + d] = l;
    }
}

// ---------------- bf16x3 tensor-core GEMM (mma.sync m16n8k16) ---------------
__device__ __forceinline__ void mma16816(float* c, const uint32* a, const uint32* b){
    asm volatile("mma.sync.aligned.m16n8k16.row.col.f32.bf16.bf16.f32 "
        "{%0,%1,%2,%3}, {%4,%5,%6,%7}, {%8,%9}, {%0,%1,%2,%3};"
        : "+f"(c[0]), "+f"(c[1]), "+f"(c[2]), "+f"(c[3])
        : "r"(a[0]), "r"(a[1]), "r"(a[2]), "r"(a[3]), "r"(b[0]), "r"(b[1]));
}

// MODE 0: C = A@B (+bias)(+add) f32.  MODE 1: gelu(A@B+bias) -> split bf16.
// MODE 2: A@B -> split bf16 (no bias).
template<int MODE>
__global__ void mma_gemm_kernel(const __nv_bfloat16* __restrict__ Ah, const __nv_bfloat16* __restrict__ Al,
                                const __nv_bfloat16* __restrict__ Bth, const __nv_bfloat16* __restrict__ Btl,
                                const float* __restrict__ bias, const float* __restrict__ add,
                                float* __restrict__ C,
                                __nv_bfloat16* __restrict__ Oh, __nv_bfloat16* __restrict__ Ol,
                                int M, int N, int K){
    __shared__ __align__(16) uint32 AsH[2][64][10], AsL[2][64][10];
    __shared__ __align__(16) uint32 BsH[2][128][10], BsL[2][128][10];
    int tid = threadIdx.x, lane = tid & 31, wid = tid >> 5;
    int g = lane >> 2, t4 = lane & 3;
    int warp_m = wid >> 1, warp_n = wid & 1;
    int m0 = blockIdx.y * 64, n0 = blockIdx.x * 128;
    int K2 = K >> 1;

    int ar[4], ac[4], ap[4], br[8], bc[8], bp[8];
    #pragma unroll
    for (int i = 0; i < 4; i++){
        int w = tid + i*128; ar[i] = w >> 3; ac[i] = w & 7;
        ap[i] = ((ac[i] & 3) << 1) | (ac[i] >> 2);
    }
    #pragma unroll
    for (int i = 0; i < 8; i++){
        int w = tid + i*128; br[i] = w >> 3; bc[i] = w & 7;
        bp[i] = ((bc[i] & 3) << 1) | (bc[i] >> 2);
    }

    uint32 pah[4], pal[4], pbh[8], pbl[8];
    #pragma unroll
    for (int i = 0; i < 4; i++){
        size_t rowoff = (size_t)(m0 + ar[i]) * K2;
        pah[i] = ((const uint32*)Ah)[rowoff + ac[i]];
        pal[i] = ((const uint32*)Al)[rowoff + ac[i]];
    }
    #pragma unroll
    for (int i = 0; i < 8; i++){
        size_t rowoff = (size_t)(n0 + br[i]) * K2;
        pbh[i] = ((const uint32*)Bth)[rowoff + bc[i]];
        pbl[i] = ((const uint32*)Btl)[rowoff + bc[i]];
    }
    #pragma unroll
    for (int i = 0; i < 4; i++){ AsH[0][ar[i]][ap[i]] = pah[i]; AsL[0][ar[i]][ap[i]] = pal[i]; }
    #pragma unroll
    for (int i = 0; i < 8; i++){ BsH[0][br[i]][bp[i]] = pbh[i]; BsL[0][br[i]][bp[i]] = pbl[i]; }
    __syncthreads();

    float acc[2][8][4];
    #pragma unroll
    for (int fm = 0; fm < 2; fm++)
        #pragma unroll
        for (int fn = 0; fn < 8; fn++)
            #pragma unroll
            for (int i = 0; i < 4; i++) acc[fm][fn][i] = 0.f;

    int nk = K >> 4;
    for (int kt = 0; kt < nk; kt++){
        int cur = kt & 1, nxt = cur ^ 1;
        if (kt + 1 < nk){
            int kw = (kt + 1) * 8;
            #pragma unroll
            for (int i = 0; i < 4; i++){
                size_t rowoff = (size_t)(m0 + ar[i]) * K2 + kw;
                pah[i] = ((const uint32*)Ah)[rowoff + ac[i]];
                pal[i] = ((const uint32*)Al)[rowoff + ac[i]];
            }
            #pragma unroll
            for (int i = 0; i < 8; i++){
                size_t rowoff = (size_t)(n0 + br[i]) * K2 + kw;
                pbh[i] = ((const uint32*)Bth)[rowoff + bc[i]];
                pbl[i] = ((const uint32*)Btl)[rowoff + bc[i]];
            }
        }
        uint32 ah[2][4], al[2][4], bh[8][2], bl[8][2];
        #pragma unroll
        for (int fm = 0; fm < 2; fm++){
            int r0 = warp_m*32 + fm*16 + g;
            uint2 u0 = *(const uint2*)&AsH[cur][r0][2*t4];
            uint2 u1 = *(const uint2*)&AsH[cur][r0+8][2*t4];
            ah[fm][0] = u0.x; ah[fm][1] = u1.x; ah[fm][2] = u0.y; ah[fm][3] = u1.y;
            uint2 v0 = *(const uint2*)&AsL[cur][r0][2*t4];
            uint2 v1 = *(const uint2*)&AsL[cur][r0+8][2*t4];
            al[fm][0] = v0.x; al[fm][1] = v1.x; al[fm][2] = v0.y; al[fm][3] = v1.y;
        }
        #pragma unroll
        for (int fn = 0; fn < 8; fn++){
            int r0 = warp_n*64 + fn*8 + g;
            uint2 u = *(const uint2*)&BsH[cur][r0][2*t4];
            bh[fn][0] = u.x; bh[fn][1] = u.y;
            uint2 v = *(const uint2*)&BsL[cur][r0][2*t4];
            bl[fn][0] = v.x; bl[fn][1] = v.y;
        }
        #pragma unroll
        for (int fn = 0; fn < 8; fn++)
            #pragma unroll
            for (int fm = 0; fm < 2; fm++){
                mma16816(acc[fm][fn], ah[fm], bh[fn]);
                mma16816(acc[fm][fn], ah[fm], bl[fn]);
                mma16816(acc[fm][fn], al[fm], bh[fn]);
            }
        if (kt + 1 < nk){
            #pragma unroll
            for (int i = 0; i < 4; i++){ AsH[nxt][ar[i]][ap[i]] = pah[i]; AsL[nxt][ar[i]][ap[i]] = pal[i]; }
            #pragma unroll
            for (int i = 0; i < 8; i++){ BsH[nxt][br[i]][bp[i]] = pbh[i]; BsL[nxt][br[i]][bp[i]] = pbl[i]; }
            __syncthreads();
        }
    }

    #pragma unroll
    for (int fm = 0; fm < 2; fm++){
        int m1 = m0 + warp_m*32 + fm*16 + g;
        int m2 = m1 + 8;
        #pragma unroll
        for (int fn = 0; fn < 8; fn++){
            int n = n0 + warp_n*64 + fn*8 + t4*2;
            float b0 = (MODE != 2 && bias) ? bias[n] : 0.f;
            float b1 = (MODE != 2 && bias) ? bias[n+1] : 0.f;
            float c0 = acc[fm][fn][0] + b0;
            float c1 = acc[fm][fn][1] + b1;
            float c2 = acc[fm][fn][2] + b0;
            float c3 = acc[fm][fn][3] + b1;
            if (MODE == 0){
                if (add){
                    c0 += add[(size_t)m1*N + n];   c1 += add[(size_t)m1*N + n + 1];
                    c2 += add[(size_t)m2*N + n];   c3 += add[(size_t)m2*N + n + 1];
                }
                *(float2*)&C[(size_t)m1*N + n] = make_float2(c0, c1);
                *(float2*)&C[(size_t)m2*N + n] = make_float2(c2, c3);
            } else {
                if (MODE == 1){
                    c0 = 0.5f*c0*(1.0f + erff(c0*0.70710678118654752f));
                    c1 = 0.5f*c1*(1.0f + erff(c1*0.70710678118654752f));
                    c2 = 0.5f*c2*(1.0f + erff(c2*0.70710678118654752f));
                    c3 = 0.5f*c3*(1.0f + erff(c3*0.70710678118654752f));
                }
                uint32 hp1, lp1, hp2, lp2;
                pack2_split(c0, c1, hp1, lp1);
                pack2_split(c2, c3, hp2, lp2);
                *(uint32*)&Oh[(size_t)m1*N + n] = hp1;
                *(uint32*)&Ol[(size_t)m1*N + n] = lp1;
                *(uint32*)&Oh[(size_t)m2*N + n] = hp2;
                *(uint32*)&Ol[(size_t)m2*N + n] = lp2;
            }
        }
    }
}

// ---------------- tensor-core attention -------------------------------------
// 128 queries/block, 256 threads (8 warps x 16 rows), grid (7, B*2).
// S = Q@K^T (bf16x3) -> reg softmax -> P repacked in regs -> O = P@V (bf16x3).
#define JT 224
#define KSTRIDE 34
#define VSTRIDE 114
__global__ void attn_mma_kernel(){
    extern __shared__ uint32 smu[];
    uint32* Kh  = smu;                        // [224][34]
    uint32* Kl  = Kh + JT*KSTRIDE;
    uint32* Vth = Kl + JT*KSTRIDE;            // [64][114] (V transposed)
    uint32* Vtl = Vth + 64*VSTRIDE;
    int bh = blockIdx.y;
    int b = bh >> 1, h = bh & 1;
    int tid = threadIdx.x, lane = tid & 31, w = tid >> 5;
    int g = lane >> 2, t4 = lane & 3;
    const uint32* kvh32 = (const uint32*)g_kvh;
    const uint32* kvl32 = (const uint32*)g_kvl;

    // stage K rows (zero for j>=NSR), permuted pairs per k16 chunk
    for (int e = tid; e < JT*32; e += 256){
        int j = e >> 5, p = e & 31;
        int c = p >> 3, pp = p & 7;
        int pos = c*8 + (((pp & 3) << 1) | (pp >> 2));
        uint32 vh = 0, vl = 0;
        if (j < NSR){
            size_t off = ((size_t)b*NSR + j)*128 + h*32 + p;
            vh = kvh32[off]; vl = kvl32[off];
        }
        Kh[j*KSTRIDE + pos] = vh;
        Kl[j*KSTRIDE + pos] = vl;
    }
    // stage V transposed: (j, d) -> Vt[d][j-pairs permuted]
    __nv_bfloat16* VthHW = (__nv_bfloat16*)Vth;
    __nv_bfloat16* VtlHW = (__nv_bfloat16*)Vtl;
    for (int e2 = tid; e2 < JT*32; e2 += 256){
        int j = e2 >> 5, e = e2 & 31;
        uint32 vh = 0, vl = 0;
        if (j < NSR){
            size_t off = ((size_t)b*NSR + j)*128 + 64 + h*32 + e;
            vh = kvh32[off]; vl = kvl32[off];
        }
        int pj = j >> 1, c = pj >> 3, pp = pj & 7;
        int pos = c*8 + (((pp & 3) << 1) | (pp >> 2));
        int hw = pos*2 + (j & 1);
        int d0 = 2*e;
        VthHW[(size_t)d0*(VSTRIDE*2) + hw]     = ((__nv_bfloat16*)&vh)[0];
        VthHW[(size_t)(d0+1)*(VSTRIDE*2) + hw] = ((__nv_bfloat16*)&vh)[1];
        VtlHW[(size_t)d0*(VSTRIDE*2) + hw]     = ((__nv_bfloat16*)&vl)[0];
        VtlHW[(size_t)(d0+1)*(VSTRIDE*2) + hw] = ((__nv_bfloat16*)&vl)[1];
    }

    // load Q A-fragments from global (clamp out-of-range rows)
    int qr0 = blockIdx.x * 128 + w * 16;
    int gq1 = min(qr0 + g, ND - 1);
    int gq2 = min(qr0 + g + 8, ND - 1);
    size_t ro1 = ((size_t)b*ND + gq1) * 64;
    size_t ro2 = ((size_t)b*ND + gq2) * 64;
    const uint32* qh32 = (const uint32*)g_qh;
    const uint32* ql32 = (const uint32*)g_ql;
    uint32 qah[4][4], qal[4][4];
    #pragma unroll
    for (int c = 0; c < 4; c++){
        qah[c][0] = qh32[ro1 + h*32 + c*8 + t4];
        qah[c][1] = qh32[ro2 + h*32 + c*8 + t4];
        qah[c][2] = qh32[ro1 + h*32 + c*8 + 4 + t4];
        qah[c][3] = qh32[ro2 + h*32 + c*8 + 4 + t4];
        qal[c][0] = ql32[ro1 + h*32 + c*8 + t4];
        qal[c][1] = ql32[ro2 + h*32 + c*8 + t4];
        qal[c][2] = ql32[ro1 + h*32 + c*8 + 4 + t4];
        qal[c][3] = ql32[ro2 + h*32 + c*8 + 4 + t4];
    }
    __syncthreads();

    // S = Q@K^T
    float sacc[28][4];
    #pragma unroll
    for (int fn = 0; fn < 28; fn++)
        #pragma unroll
        for (int i = 0; i < 4; i++) sacc[fn][i] = 0.f;
    #pragma unroll
    for (int c = 0; c < 4; c++)
        #pragma unroll
        for (int fn = 0; fn < 28; fn++){
            int r0 = fn*8 + g;
            uint2 uh = *(const uint2*)&Kh[r0*KSTRIDE + c*8 + 2*t4];
            uint2 ul = *(const uint2*)&Kl[r0*KSTRIDE + c*8 + 2*t4];
            uint32 bhf[2] = {uh.x, uh.y}, blf[2] = {ul.x, ul.y};
            mma16816(sacc[fn], qah[c], bhf);
            mma16816(sacc[fn], qah[c], blf);
            mma16816(sacc[fn], qal[c], bhf);
        }

    // register softmax over valid j < NSR (rows g, g+8 per thread)
    const float scale = 0.17677669529663687f;   // 32^-0.5
    float mx0 = -1e30f, mx1 = -1e30f;
    #pragma unroll
    for (int fn = 0; fn < 28; fn++){
        int jb = fn*8 + t4*2;
        #pragma unroll
        for (int i = 0; i < 4; i++){
            int j = jb + (i & 1);
            float s = sacc[fn][i] * scale;
            s = (j < NSR) ? s : -1e30f;
            sacc[fn][i] = s;
            if (i < 2) mx0 = fmaxf(mx0, s); else mx1 = fmaxf(mx1, s);
        }
    }
    mx0 = fmaxf(mx0, __shfl_xor_sync(0xffffffffu, mx0, 1));
    mx0 = fmaxf(mx0, __shfl_xor_sync(0xffffffffu, mx0, 2));
    mx1 = fmaxf(mx1, __shfl_xor_sync(0xffffffffu, mx1, 1));
    mx1 = fmaxf(mx1, __shfl_xor_sync(0xffffffffu, mx1, 2));
    float sum0 = 0.f, sum1 = 0.f;
    #pragma unroll
    for (int fn = 0; fn < 28; fn++){
        #pragma unroll
        for (int i = 0; i < 4; i++){
            float p = expf(sacc[fn][i] - ((i < 2) ? mx0 : mx1));
            sacc[fn][i] = p;
            if (i < 2) sum0 += p; else sum1 += p;
        }
    }
    sum0 += __shfl_xor_sync(0xffffffffu, sum0, 1);
    sum0 += __shfl_xor_sync(0xffffffffu, sum0, 2);
    sum1 += __shfl_xor_sync(0xffffffffu, sum1, 1);
    sum1 += __shfl_xor_sync(0xffffffffu, sum1, 2);

    // O = P@V : pack P frags per k-chunk in regs, consume immediately
    float oacc[8][4];
    #pragma unroll
    for (int fn = 0; fn < 8; fn++)
        #pragma unroll
        for (int i = 0; i < 4; i++) oacc[fn][i] = 0.f;
    #pragma unroll
    for (int kc = 0; kc < 14; kc++){
        uint32 ph[4], pl[4];
        pack2_split(sacc[2*kc][0],   sacc[2*kc][1],   ph[0], pl[0]);
        pack2_split(sacc[2*kc][2],   sacc[2*kc][3],   ph[1], pl[1]);
        pack2_split(sacc[2*kc+1][0], sacc[2*kc+1][1], ph[2], pl[2]);
        pack2_split(sacc[2*kc+1][2], sacc[2*kc+1][3], ph[3], pl[3]);
        #pragma unroll
        for (int fn = 0; fn < 8; fn++){
            int r0 = fn*8 + g;
            uint2 uh = *(const uint2*)&Vth[r0*VSTRIDE + kc*8 + 2*t4];
            uint2 ul = *(const uint2*)&Vtl[r0*VSTRIDE + kc*8 + 2*t4];
            uint32 bhf[2] = {uh.x, uh.y}, blf[2] = {ul.x, ul.y};
            mma16816(oacc[fn], ph, bhf);
            mma16816(oacc[fn], ph, blf);
            mma16816(oacc[fn], pl, bhf);
        }
    }

    // epilogue: normalize rows, split-bf16 into concat buffer cols [0:128)
    float inv0 = 1.0f / sum0, inv1 = 1.0f / sum1;
    int q1 = qr0 + g, q2 = qr0 + g + 8;
    #pragma unroll
    for (int fn = 0; fn < 8; fn++){
        int d = fn*8 + t4*2;
        if (q1 < ND){
            size_t cb = ((size_t)b*ND + q1)*KCAT + h*64 + d;
            uint32 hp, lp;
            pack2_split(oacc[fn][0]*inv0, oacc[fn][1]*inv0, hp, lp);
            *(uint32*)&g_cath[cb] = hp;
            *(uint32*)&g_catl[cb] = lp;
        }
        if (q2 < ND){
            size_t cb = ((size_t)b*ND + q2)*KCAT + h*64 + d;
            uint32 hp, lp;
            pack2_split(oacc[fn][2]*inv1, oacc[fn][3]*inv1, hp, lp);
            *(uint32*)&g_cath[cb] = hp;
            *(uint32*)&g_catl[cb] = lp;
        }
    }
}

// ---------------- bilinear grid-sample of pos_embed, add into out -----------
__global__ void possample_kernel(const float* __restrict__ pe, float* __restrict__ out){
    int warp = (blockIdx.x * blockDim.x + threadIdx.x) >> 5;
    int lane = threadIdx.x & 31;
    if (warp >= Bv*ND) return;
    float px = g_posd[(size_t)warp*2], py = g_posd[(size_t)warp*2 + 1];
    float gx = px*2.f - 1.f, gy = py*2.f - 1.f;
    float ix = ((gx + 1.f)*56.f - 1.f)*0.5f;
    float iy = ((gy + 1.f)*56.f - 1.f)*0.5f;
    float x0 = floorf(ix), y0 = floorf(iy);
    float wx = ix - x0,   wy = iy - y0;
    float accv[4] = {};
    #pragma unroll
    for (int cy = 0; cy < 2; cy++){
        #pragma unroll
        for (int cx = 0; cx < 2; cx++){
            float xc = x0 + cx, yc = y0 + cy;
            float wgt = (cx ? wx : 1.f-wx) * (cy ? wy : 1.f-wy);
            bool valid = (xc >= 0.f) && (xc < 56.f) && (yc >= 0.f) && (yc < 56.f);
            float wv = valid ? wgt : 0.f;
            int xi = (int)fminf(fmaxf(xc, 0.f), 55.f);
            int yi = (int)fminf(fmaxf(yc, 0.f), 55.f);
            int lin = yi*56 + xi;
            #pragma unroll
            for (int r = 0; r < 4; r++)
                accv[r] += pe[(size_t)lin*128 + lane + 32*r] * wv;
        }
    }
    #pragma unroll
    for (int r = 0; r < 4; r++)
        out[(size_t)warp*128 + lane + 32*r] += accv[r];
}

// ---------------- launcher ---------------------------------------------------
extern "C" void kernel_launch(void* const* d_in, const int* in_sizes, int n_in,
                              void* d_out, int out_size){
    const float* x        = (const float*)d_in[0];
    const float* pos      = (const float*)d_in[1];
    const float* pos_embed= (const float*)d_in[2];
    const float* noise_u  = (const float*)d_in[3];
    const float* norm_g   = (const float*)d_in[4];
    const float* norm_b   = (const float*)d_in[5];
    const float* conf_w   = (const float*)d_in[6];
    const float* conf_b   = (const float*)d_in[7];
    const float* n1g      = (const float*)d_in[8];
    const float* n1b      = (const float*)d_in[9];
    const float* q_w      = (const float*)d_in[10];
    const float* k_w      = (const float*)d_in[11];
    const float* v_w      = (const float*)d_in[12];
    const float* proj_w   = (const float*)d_in[13];
    const float* proj_b   = (const float*)d_in[14];
    const float* sr_w     = (const float*)d_in[15];
    const float* sr_b     = (const float*)d_in[16];
    const float* srn_g    = (const float*)d_in[17];
    const float* srn_b    = (const float*)d_in[18];
    const float* fc_w     = (const float*)d_in[19];
    const float* fc_b     = (const float*)d_in[20];
    const float* n2g      = (const float*)d_in[21];
    const float* n2b      = (const float*)d_in[22];
    const float* fc1_w    = (const float*)d_in[23];
    const float* fc1_b    = (const float*)d_in[24];
    const float* fc2_w    = (const float*)d_in[25];
    const float* fc2_b    = (const float*)d_in[26];
    float* out = (float*)d_out;

    float *p_xs, *p_x2, *p_biaspf;
    __nv_bfloat16 *p_xnh, *p_xnl, *p_xsh, *p_xsl, *p_cath, *p_catl;
    __nv_bfloat16 *p_qh, *p_ql, *p_kvh, *p_kvl;
    __nv_bfloat16 *p_xn2h, *p_xn2l, *p_hidh, *p_hidl;
    __nv_bfloat16 *p_w1h, *p_w1l, *p_w2h, *p_w2l, *p_wqh, *p_wql, *p_wkvh, *p_wkvl, *p_wpfh, *p_wpfl;
    cudaGetSymbolAddress((void**)&p_xs,    g_xs);
    cudaGetSymbolAddress((void**)&p_x2,    g_x2);
    cudaGetSymbolAddress((void**)&p_biaspf,g_biaspf);
    cudaGetSymbolAddress((void**)&p_xnh,   g_xnh);
    cudaGetSymbolAddress((void**)&p_xnl,   g_xnl);
    cudaGetSymbolAddress((void**)&p_xsh,   g_xsh);
    cudaGetSymbolAddress((void**)&p_xsl,   g_xsl);
    cudaGetSymbolAddress((void**)&p_qh,    g_qh);
    cudaGetSymbolAddress((void**)&p_ql,    g_ql);
    cudaGetSymbolAddress((void**)&p_kvh,   g_kvh);
    cudaGetSymbolAddress((void**)&p_kvl,   g_kvl);
    cudaGetSymbolAddress((void**)&p_cath,  g_cath);
    cudaGetSymbolAddress((void**)&p_catl,  g_catl);
    cudaGetSymbolAddress((void**)&p_xn2h,  g_xn2h);
    cudaGetSymbolAddress((void**)&p_xn2l,  g_xn2l);
    cudaGetSymbolAddress((void**)&p_hidh,  g_hidh);
    cudaGetSymbolAddress((void**)&p_hidl,  g_hidl);
    cudaGetSymbolAddress((void**)&p_w1h,   g_w1h);
    cudaGetSymbolAddress((void**)&p_w1l,   g_w1l);
    cudaGetSymbolAddress((void**)&p_w2h,   g_w2h);
    cudaGetSymbolAddress((void**)&p_w2l,   g_w2l);
    cudaGetSymbolAddress((void**)&p_wqh,   g_wqh);
    cudaGetSymbolAddress((void**)&p_wql,   g_wql);
    cudaGetSymbolAddress((void**)&p_wkvh,  g_wkvh);
    cudaGetSymbolAddress((void**)&p_wkvl,  g_wkvl);
    cudaGetSymbolAddress((void**)&p_wpfh,  g_wpfh);
    cudaGetSymbolAddress((void**)&p_wpfl,  g_wpfl);

    zero_kernel<<<4096, 256>>>();
    prep_kernel<<<(180288 + 255)/256, 256>>>(fc1_w, fc2_w, q_w, k_w, v_w, proj_w, fc_w, proj_b, fc_b);

    // fused LN+scatter+score (coalesced smem staging)
    size_t ls_smem = (256*64 + 512) * sizeof(float);
    cudaFuncSetAttribute(lnscore_kernel, cudaFuncAttributeMaxDynamicSharedMemorySize, (int)ls_smem);
    lnscore_kernel<<<Bv*Nv/256, 256, ls_smem>>>(x, pos, noise_u, n1g, n1b, norm_g, norm_b, conf_w, conf_b);

    topk_kernel<<<Bv, 1024>>>();
    gather_ln_kernel<<<(Bv*ND + 7)/8, 256>>>(x, pos, n1g, n1b);
    blur_kernel<<<(Bv*Nv*Cv + 255)/256, 256>>>();
    srconv_kernel<<<196, 256>>>(sr_w, sr_b);
    ln64_split_kernel<<<(MSR + 7)/8, 256>>>(p_xs, p_xsh, p_xsl, srn_g, srn_b, MSR);

    // q = xn @ q_w ; [k|v] = xs @ [k_w|v_w]   -> split bf16 outputs
    mma_gemm_kernel<2><<<dim3(1, MROWS/64), 128>>>(
        p_xnh, p_xnl, p_wqh, p_wql, nullptr, nullptr, nullptr, p_qh, p_ql, MROWS, 128, 64);
    mma_gemm_kernel<2><<<dim3(2, MSR/64), 128>>>(
        p_xsh, p_xsl, p_wkvh, p_wkvl, nullptr, nullptr, nullptr, p_kvh, p_kvl, MSR, 256, 64);

    // tensor-core attention -> concat buffer cols [0:128)
    size_t attn_smem = (size_t)(JT*KSTRIDE*2 + 64*VSTRIDE*2) * sizeof(uint32);
    cudaFuncSetAttribute(attn_mma_kernel, cudaFuncAttributeMaxDynamicSharedMemorySize, (int)attn_smem);
    attn_mma_kernel<<<dim3(7, Bv*2), 256, attn_smem>>>();

    // x2 = [oatt|xdown] @ [proj_w;fc_w] + (proj_b+fc_b)   (K=192)
    mma_gemm_kernel<0><<<dim3(1, MROWS/64), 128>>>(
        p_cath, p_catl, p_wpfh, p_wpfl, p_biaspf, nullptr, p_x2, nullptr, nullptr, MROWS, 128, KCAT);

    // LN2 -> split bf16 xn2
    ln128_split_kernel<<<(Bv*ND + 7)/8, 256>>>(p_x2, p_xn2h, p_xn2l, n2g, n2b, Bv*ND);

    // hid = gelu(xn2 @ fc1 + b1) -> split bf16 (tensor cores)
    mma_gemm_kernel<1><<<dim3(HIDN/128, MROWS/64), 128>>>(
        p_xn2h, p_xn2l, p_w1h, p_w1l, fc1_b, nullptr, nullptr, p_hidh, p_hidl,
        MROWS, HIDN, DOUT);
    // out = x2 + hid @ fc2 + b2 (tensor cores)
    mma_gemm_kernel<0><<<dim3(DOUT/128, MROWS/64), 128>>>(
        p_hidh, p_hidl, p_w2h, p_w2l, fc2_b, p_x2, out, nullptr, nullptr,
        MROWS, DOUT, HIDN);

    // out += grid_sample(pos_embed)
    possample_kernel<<<(Bv*ND + 7)/8, 256>>>(pos_embed, out);
}

// round 16
// speedup vs baseline: 1.1102x; 1.0097x over previous
#include <cuda_runtime.h>
#include <cuda_bf16.h>
#include <math.h>

typedef unsigned int uint32;

// Problem constants (fixed by setup_inputs)
#define Bv 64
#define Nv 3136
#define Cv 64
#define DOUT 128
#define Wv 56
#define NG 49
#define SAMPLE 784
#define ND 833            // NG + SAMPLE
#define NS 3087           // Nv - NG
#define NSR 196           // (56/4)^2
#define HIDN 512
#define MROWS (Bv*ND)     // 53312
#define MSR   (Bv*NSR)    // 12544
#define KCAT  192         // 128 (oatt) + 64 (xdown)

// ---------------- scratch (static device memory; allocation-free) ----------
__device__ float g_scores[Bv*NS];
__device__ int   g_idx  [Bv*SAMPLE];
__device__ float g_posd [Bv*ND*2];
__device__ float g_segf [Bv*Nv*Cv];
__device__ float g_cnt  [Bv*Nv];
__device__ float g_fmap [Bv*Nv*Cv];
__device__ float g_xs   [MSR*Cv];
__device__ float g_x2   [MROWS*DOUT];
// bf16-split operands for tensor-core GEMMs
__device__ __align__(16) __nv_bfloat16 g_xnh[MROWS*Cv];
__device__ __align__(16) __nv_bfloat16 g_xnl[MROWS*Cv];
__device__ __align__(16) __nv_bfloat16 g_xsh[MSR*Cv];
__device__ __align__(16) __nv_bfloat16 g_xsl[MSR*Cv];
__device__ __align__(16) __nv_bfloat16 g_qh [MROWS*DOUT];
__device__ __align__(16) __nv_bfloat16 g_ql [MROWS*DOUT];
__device__ __align__(16) __nv_bfloat16 g_kvh[MSR*256];
__device__ __align__(16) __nv_bfloat16 g_kvl[MSR*256];
__device__ __align__(16) __nv_bfloat16 g_cath[(size_t)MROWS*KCAT];
__device__ __align__(16) __nv_bfloat16 g_catl[(size_t)MROWS*KCAT];
__device__ __align__(16) __nv_bfloat16 g_xn2h[MROWS*DOUT];
__device__ __align__(16) __nv_bfloat16 g_xn2l[MROWS*DOUT];
__device__ __align__(16) __nv_bfloat16 g_hidh[(size_t)MROWS*HIDN];
__device__ __align__(16) __nv_bfloat16 g_hidl[(size_t)MROWS*HIDN];
__device__ __align__(16) __nv_bfloat16 g_w1h[HIDN*DOUT];   // [n][k]
__device__ __align__(16) __nv_bfloat16 g_w1l[HIDN*DOUT];
__device__ __align__(16) __nv_bfloat16 g_w2h[DOUT*HIDN];
__device__ __align__(16) __nv_bfloat16 g_w2l[DOUT*HIDN];
__device__ __align__(16) __nv_bfloat16 g_wqh[DOUT*Cv];
__device__ __align__(16) __nv_bfloat16 g_wql[DOUT*Cv];
__device__ __align__(16) __nv_bfloat16 g_wkvh[256*Cv];
__device__ __align__(16) __nv_bfloat16 g_wkvl[256*Cv];
__device__ __align__(16) __nv_bfloat16 g_wpfh[DOUT*KCAT];
__device__ __align__(16) __nv_bfloat16 g_wpfl[DOUT*KCAT];
__device__ float g_biaspf[DOUT];

__device__ __forceinline__ float warp_sum(float v){
    #pragma unroll
    for (int o = 16; o; o >>= 1) v = __fadd_rn(v, __shfl_xor_sync(0xffffffffu, v, o));
    return v;
}
__device__ __forceinline__ void bsplit(float v, __nv_bfloat16& h, __nv_bfloat16& l){
    h = __float2bfloat16(v);
    l = __float2bfloat16(v - __bfloat162float(h));
}
__device__ __forceinline__ void pack2_split(float a, float b, uint32& hi, uint32& lo){
    __nv_bfloat16 ha, la, hb, lb;
    bsplit(a, ha, la); bsplit(b, hb, lb);
    __nv_bfloat162 ph; ph.x = ha; ph.y = hb;
    __nv_bfloat162 pl; pl.x = la; pl.y = lb;
    hi = *(uint32*)&ph; lo = *(uint32*)&pl;
}

// ---------------- zero segf/cnt -------------------------------------------
__global__ void zero_kernel(){
    int stride = gridDim.x * blockDim.x;
    int t = blockIdx.x * blockDim.x + threadIdx.x;
    for (int i = t; i < Bv*Nv*Cv; i += stride) g_segf[i] = 0.f;
    for (int i = t; i < Bv*Nv;    i += stride) g_cnt[i]  = 0.f;
}

// ---------------- unified weight prep: transpose+split all weights ---------
__global__ void prep_kernel(const float* __restrict__ fc1_w, const float* __restrict__ fc2_w,
                            const float* __restrict__ q_w, const float* __restrict__ k_w,
                            const float* __restrict__ v_w, const float* __restrict__ proj_w,
                            const float* __restrict__ fc_w,
                            const float* __restrict__ proj_b, const float* __restrict__ fc_b){
    int t = blockIdx.x * blockDim.x + threadIdx.x;
    __nv_bfloat16 h, l;
    if (t < 65536){                      // fc1
        int n = t / DOUT, k = t % DOUT;
        bsplit(fc1_w[(size_t)k*HIDN + n], h, l);
        g_w1h[t] = h; g_w1l[t] = l; return;
    }
    t -= 65536;
    if (t < 65536){                      // fc2
        int n = t / HIDN, k = t % HIDN;
        bsplit(fc2_w[(size_t)k*DOUT + n], h, l);
        g_w2h[t] = h; g_w2l[t] = l; return;
    }
    t -= 65536;
    if (t < 8192){                       // q
        int n = t / Cv, k = t % Cv;
        bsplit(q_w[(size_t)k*DOUT + n], h, l);
        g_wqh[t] = h; g_wql[t] = l; return;
    }
    t -= 8192;
    if (t < 8192){                       // k -> wkv rows [0:128)
        int n = t / Cv, k = t % Cv;
        bsplit(k_w[(size_t)k*DOUT + n], h, l);
        g_wkvh[t] = h; g_wkvl[t] = l; return;
    }
    t -= 8192;
    if (t < 8192){                       // v -> wkv rows [128:256)
        int n = t / Cv, k = t % Cv;
        bsplit(v_w[(size_t)k*DOUT + n], h, l);
        g_wkvh[128*Cv + t] = h; g_wkvl[128*Cv + t] = l; return;
    }
    t -= 8192;
    if (t < 16384){                      // proj -> wpf[n*192+k]
        int n = t / DOUT, k = t % DOUT;
        bsplit(proj_w[(size_t)k*DOUT + n], h, l);
        g_wpfh[(size_t)n*KCAT + k] = h; g_wpfl[(size_t)n*KCAT + k] = l; return;
    }
    t -= 16384;
    if (t < 8192){                       // fc -> wpf[n*192+128+k]
        int n = t / Cv, k = t % Cv;
        bsplit(fc_w[(size_t)k*DOUT + n], h, l);
        g_wpfh[(size_t)n*KCAT + 128 + k] = h; g_wpfl[(size_t)n*KCAT + 128 + k] = l; return;
    }
    t -= 8192;
    if (t < DOUT) g_biaspf[t] = proj_b[t] + fc_b[t];
}

// ------- fused LN+scatter+score: 256 tokens staged in smem per block -------
__global__ void lnscore_kernel(const float* __restrict__ x, const float* __restrict__ pos,
                               const float* __restrict__ noise_u,
                               const float* __restrict__ n1g, const float* __restrict__ n1b,
                               const float* __restrict__ ng, const float* __restrict__ nb,
                               const float* __restrict__ cw, const float* __restrict__ cb){
    extern __shared__ float sx[];            // [256*64] x rows + [512] pos
    float* spos = sx + 256*64;
    int tid = threadIdx.x, lane = tid & 31, w = tid >> 5;
    size_t t0 = (size_t)blockIdx.x * 256;
    const float4* src = (const float4*)(x + t0*64);
    float4* dst = (float4*)sx;
    #pragma unroll
    for (int i = 0; i < 16; i++) dst[tid + i*256] = src[tid + i*256];
    #pragma unroll
    for (int i = 0; i < 2; i++) spos[tid + i*256] = pos[t0*2 + tid + i*256];
    __syncthreads();

    // phase 1: LN + scatter (warp per token, 32 tokens/warp)
    for (int it = 0; it < 32; it++){
        int tk = w*32 + it;
        size_t t = t0 + tk;
        int b = (int)(t / Nv);
        const float* xr = sx + tk*64;
        float v0 = xr[lane], v1 = xr[lane+32];
        float m = warp_sum(v0 + v1) * (1.0f/64.0f);
        float d0 = v0 - m, d1 = v1 - m;
        float var = warp_sum(d0*d0 + d1*d1) * (1.0f/64.0f);
        float rstd = rsqrtf(var + 1e-5f);
        float xsn0 = d0*rstd*n1g[lane]    + n1b[lane];
        float xsn1 = d1*rstd*n1g[lane+32] + n1b[lane+32];
        int p = 0;
        if (lane == 0){
            float px = fminf(fmaxf(spos[tk*2],   0.f), 1.f) * 55.f;
            float py = fminf(fmaxf(spos[tk*2+1], 0.f), 1.f) * 55.f;
            p = (int)rintf(px) + (int)rintf(py) * Wv;   // half-to-even
        }
        p = __shfl_sync(0xffffffffu, p, 0);
        size_t base = ((size_t)b*Nv + p)*64;
        atomicAdd(&g_segf[base + lane],      xsn0);
        atomicAdd(&g_segf[base + lane + 32], xsn1);
        if (lane == 0) atomicAdd(&g_cnt[b*Nv + p], 1.0f);
    }

    // phase 2: score (thread per token, serial XLA-CPU semantics)
    size_t t = t0 + tid;
    int b = (int)(t / Nv), n = (int)(t % Nv);
    if (n >= NG){
        const float* r = sx + tid*64;
        float s = 0.f;
        for (int k = 0; k < 64; k++) s = __fadd_rn(s, r[k]);
        float m = __fdiv_rn(s, 64.0f);
        float vs = 0.f;
        for (int k = 0; k < 64; k++){
            float d = __fsub_rn(r[k], m);
            vs = __fadd_rn(vs, __fmul_rn(d, d));
        }
        float var = __fdiv_rn(vs, 64.0f);
        float rstd = __fdiv_rn(1.0f, sqrtf(__fadd_rn(var, 1e-5f)));  // CPU rsqrt
        float c = 0.f;
        for (int k = 0; k < 64; k++){
            float h = __fmul_rn(__fsub_rn(r[k], m), rstd);
            float tt = __fadd_rn(__fmul_rn(h, ng[k]), nb[k]);
            c = __fadd_rn(c, __fmul_rn(tt, cw[k]));
        }
        float u = noise_u[(size_t)b*NS + (n-NG)];
        float a1 = __fadd_rn(u, 1e-6f);
        float l1 = (float)log((double)a1);
        float inner = __fadd_rn(-l1, 1e-6f);
        float l2 = (float)log((double)inner);
        float noise = -l2;
        g_scores[(size_t)b*NS + (n-NG)] = __fadd_rn(__fadd_rn(c, cb[0]), noise);
    }
}

// ---------------- exact jax top-k: register/shfl bitonic sort ---------------
// 4096 elements, element i = 4*tid + e held in registers; j<=2 in-thread,
// j=4..64 via shfl, j>=128 via smem (15 barrier phases instead of 78).
__global__ void topk_kernel(){
    __shared__ unsigned long long keys[4096];
    int b = blockIdx.x, tid = threadIdx.x;
    unsigned long long v[4];
    #pragma unroll
    for (int e = 0; e < 4; e++){
        int i = (tid<<2)|e;
        unsigned long long kk = ~0ULL;
        if (i < NS){
            unsigned u = __float_as_uint(g_scores[(size_t)b*NS + i]);
            u = (u & 0x80000000u) ? ~u : (u | 0x80000000u);
            kk = ((unsigned long long)(~u) << 32) | (unsigned)i;
        }
        v[e] = kk;
    }
    for (int k = 2; k <= 4096; k <<= 1){
        for (int j = k >> 1; j > 0; j >>= 1){
            if (j >= 128){
                #pragma unroll
                for (int e = 0; e < 4; e++) keys[(tid<<2)|e] = v[e];
                __syncthreads();
                #pragma unroll
                for (int e = 0; e < 4; e++){
                    int i = (tid<<2)|e;
                    unsigned long long pv = keys[i ^ j];
                    bool isLower = (i & j) == 0;
                    bool up = (i & k) == 0;
                    bool keepMin = (up == isLower);
                    v[e] = (keepMin == (v[e] <= pv)) ? v[e] : pv;
                }
                __syncthreads();
            } else if (j >= 4){
                int jj = j >> 2;
                #pragma unroll
                for (int e = 0; e < 4; e++){
                    int i = (tid<<2)|e;
                    unsigned long long pv = __shfl_xor_sync(0xffffffffu, v[e], jj);
                    bool isLower = (tid & jj) == 0;
                    bool up = (i & k) == 0;
                    bool keepMin = (up == isLower);
                    v[e] = (keepMin == (v[e] <= pv)) ? v[e] : pv;
                }
            } else if (j == 2){
                #pragma unroll
                for (int e = 0; e < 2; e++){
                    int i = (tid<<2)|e;
                    bool up = ((i & k) == 0);
                    unsigned long long a = v[e], c = v[e+2];
                    if ((a > c) == up){ v[e] = c; v[e+2] = a; }
                }
            } else {
                #pragma unroll
                for (int e = 0; e < 4; e += 2){
                    int i = (tid<<2)|e;
                    bool up = ((i & k) == 0);
                    unsigned long long a = v[e], c = v[e+1];
                    if ((a > c) == up){ v[e] = c; v[e+1] = a; }
                }
            }
        }
    }
    #pragma unroll
    for (int e = 0; e < 4; e++){
        int i = (tid<<2)|e;
        if (i < SAMPLE) g_idx[b*SAMPLE + i] = (int)(unsigned)(v[e] & 0xFFFFFFFFULL);
    }
}

// ---- gather: xdown split -> cat cols [128:192), xn split, pos_down --------
__global__ void gather_ln_kernel(const float* __restrict__ x, const float* __restrict__ pos,
                                 const float* __restrict__ n1g, const float* __restrict__ n1b){
    int warp = (blockIdx.x * blockDim.x + threadIdx.x) >> 5;
    int lane = threadIdx.x & 31;
    if (warp >= Bv*ND) return;
    int b = warp / ND, j = warp % ND;
    int n = (j < NG) ? j : (NG + g_idx[b*SAMPLE + (j - NG)]);
    const float* xr = x + ((size_t)b*Nv + n) * Cv;
    float v0 = xr[lane], v1 = xr[lane+32];
    {
        __nv_bfloat16 h, l;
        size_t cb = (size_t)warp*KCAT + 128;
        bsplit(v0, h, l); g_cath[cb + lane]      = h; g_catl[cb + lane]      = l;
        bsplit(v1, h, l); g_cath[cb + lane + 32] = h; g_catl[cb + lane + 32] = l;
    }
    float m = warp_sum(v0 + v1) * (1.0f/64.0f);
    float d0 = v0 - m, d1 = v1 - m;
    float var = warp_sum(d0*d0 + d1*d1) * (1.0f/64.0f);
    float rstd = rsqrtf(var + 1e-5f);
    float xn0 = d0*rstd*n1g[lane]    + n1b[lane];
    float xn1 = d1*rstd*n1g[lane+32] + n1b[lane+32];
    {
        __nv_bfloat16 h, l;
        bsplit(xn0, h, l); g_xnh[(size_t)warp*64 + lane]      = h; g_xnl[(size_t)warp*64 + lane]      = l;
        bsplit(xn1, h, l); g_xnh[(size_t)warp*64 + lane + 32] = h; g_xnl[(size_t)warp*64 + lane + 32] = l;
    }
    if (lane < 2) g_posd[(size_t)warp*2 + lane] = pos[((size_t)b*Nv + n)*2 + lane];
}

// ---------------- normalize + 3x3 gaussian reconstruct fused ----------------
__global__ void blur_kernel(){
    int t = blockIdx.x * blockDim.x + threadIdx.x;
    if (t >= Bv*Nv*Cv) return;
    int c = t & 63; int q = t >> 6; int hw = q % Nv; int b = q / Nv;
    int yy = hw / Wv, xx = hw % Wv;
    const float e1 = 0.88249690f, e2 = 0.77880078f;
    const float S  = 1.0f + 4.0f*(e1 + e2);
    const float wt[3] = {1.0f/S, e1/S, e2/S};
    float cc = g_cnt[b*Nv + hw];
    float maskc = cc > 0.f ? 1.f : 0.f;
    float featc = (g_segf[t] / (cc + 1e-6f)) * maskc;
    float bf = 0.f, bm = 0.f;
    #pragma unroll
    for (int dy = -1; dy <= 1; dy++){
        #pragma unroll
        for (int dx = -1; dx <= 1; dx++){
            int y2 = yy + dy, x2 = xx + dx;
            if (y2 >= 0 && y2 < Wv && x2 >= 0 && x2 < Wv){
                int hw2 = y2*Wv + x2;
                float cn = g_cnt[b*Nv + hw2];
                float mn = cn > 0.f ? 1.f : 0.f;
                float fn = (g_segf[((size_t)b*Nv + hw2)*64 + c] / (cn + 1e-6f)) * mn;
                float w = wt[dy*dy + dx*dx];
                bf += w * fn; bm += w * mn;
            }
        }
    }
    float fi = bf / (bm + 1e-6f);
    fi = (bm > 0.f) ? fi : 0.f;
    g_fmap[t] = featc + (1.f - maskc) * fi;
}

// ---------------- sr 4x4 stride-4 conv as tiled GEMM (fp32) -----------------
__global__ void srconv_kernel(const float* __restrict__ srw, const float* __restrict__ srb){
    __shared__ float As[16][64];
    __shared__ float Bs[16][64];
    int m0 = blockIdx.x * 64;
    int tid = threadIdx.x, tx = tid & 15, ty = tid >> 4;
    float acc[4][4] = {};
    for (int k0 = 0; k0 < 1024; k0 += 16){
        #pragma unroll
        for (int i = 0; i < 4; i++){
            int e = tid + i*256;
            int kk = e & 15, mm = e >> 4;
            int m = m0 + mm, k = k0 + kk;
            int b = m / NSR, s2 = m % NSR;
            int oy = s2 / 14, ox = s2 % 14;
            int kyx = k >> 6, ci = k & 63;
            int ky = kyx >> 2, kx = kyx & 3;
            As[kk][mm] = g_fmap[(((size_t)b*Nv) + (oy*4+ky)*Wv + (ox*4+kx))*64 + ci];
        }
        #pragma unroll
        for (int i = 0; i < 4; i++){
            int e = tid + i*256;
            int n = e & 63, kk = e >> 6;
            int k = k0 + kk;
            int kyx = k >> 6, ci = k & 63;
            Bs[kk][n] = srw[(size_t)n*1024 + ci*16 + kyx];
        }
        __syncthreads();
        #pragma unroll
        for (int kk = 0; kk < 16; kk++){
            float a[4], bb[4];
            #pragma unroll
            for (int i = 0; i < 4; i++) a[i] = As[kk][ty*4+i];
            #pragma unroll
            for (int j = 0; j < 4; j++) bb[j] = Bs[kk][tx*4+j];
            #pragma unroll
            for (int i = 0; i < 4; i++)
                #pragma unroll
                for (int j = 0; j < 4; j++) acc[i][j] += a[i]*bb[j];
        }
        __syncthreads();
    }
    #pragma unroll
    for (int i = 0; i < 4; i++)
        #pragma unroll
        for (int j = 0; j < 4; j++){
            int m = m0 + ty*4 + i, n = tx*4 + j;
            g_xs[(size_t)m*64 + n] = acc[i][j] + srb[n];
        }
}

// ---------------- ln64 -> split bf16 (feeds k/v mma) ------------------------
__global__ void ln64_split_kernel(const float* __restrict__ in,
                                  __nv_bfloat16* __restrict__ oh, __nv_bfloat16* __restrict__ ol,
                                  const float* __restrict__ g, const float* __restrict__ b, int rows){
    int warp = (blockIdx.x * blockDim.x + threadIdx.x) >> 5;
    int lane = threadIdx.x & 31;
    if (warp >= rows) return;
    const float* xr = in + (size_t)warp*64;
    float v0 = xr[lane], v1 = xr[lane+32];
    float m = warp_sum(v0+v1) * (1.0f/64.0f);
    float d0 = v0-m, d1 = v1-m;
    float rstd = rsqrtf(warp_sum(d0*d0+d1*d1)*(1.0f/64.0f) + 1e-5f);
    float o0 = d0*rstd*g[lane]    + b[lane];
    float o1 = d1*rstd*g[lane+32] + b[lane+32];
    __nv_bfloat16 h, l;
    bsplit(o0, h, l); oh[(size_t)warp*64 + lane]      = h; ol[(size_t)warp*64 + lane]      = l;
    bsplit(o1, h, l); oh[(size_t)warp*64 + lane + 32] = h; ol[(size_t)warp*64 + lane + 32] = l;
}

// ---------------- bf16x3 tensor-core GEMM (mma.sync m16n8k16) ---------------
__device__ __forceinline__ void mma16816(float* c, const uint32* a, const uint32* b){
    asm volatile("mma.sync.aligned.m16n8k16.row.col.f32.bf16.bf16.f32 "
        "{%0,%1,%2,%3}, {%4,%5,%6,%7}, {%8,%9}, {%0,%1,%2,%3};"
        : "+f"(c[0]), "+f"(c[1]), "+f"(c[2]), "+f"(c[3])
        : "r"(a[0]), "r"(a[1]), "r"(a[2]), "r"(a[3]), "r"(b[0]), "r"(b[1]));
}

// MODE 0: C = A@B (+bias)(+add) f32.
// MODE 1: gelu(A@B+bias) -> split bf16.
// MODE 2: A@B -> split bf16 (no bias).
// MODE 3: x2 = A@B+bias -> C (f32) AND LN(x2; aux1=gamma, aux2=beta) -> split bf16.
//         (requires N==128 and gridDim.x==1: full rows per block)
// MODE 4: C = A@B + bias + add + grid_sample(aux1=pos_embed via g_posd) f32.
template<int MODE>
__global__ void mma_gemm_kernel(const __nv_bfloat16* __restrict__ Ah, const __nv_bfloat16* __restrict__ Al,
                                const __nv_bfloat16* __restrict__ Bth, const __nv_bfloat16* __restrict__ Btl,
                                const float* __restrict__ bias, const float* __restrict__ add,
                                float* __restrict__ C,
                                __nv_bfloat16* __restrict__ Oh, __nv_bfloat16* __restrict__ Ol,
                                const float* __restrict__ aux1, const float* __restrict__ aux2,
                                int M, int N, int K){
    __shared__ __align__(16) uint32 AsH[2][64][10], AsL[2][64][10];
    __shared__ __align__(16) uint32 BsH[2][128][10], BsL[2][128][10];
    __shared__ float sred[64][2][2];   // MODE 3 row partials [row][warp_n][sum,sq]
    int tid = threadIdx.x, lane = tid & 31, wid = tid >> 5;
    int g = lane >> 2, t4 = lane & 3;
    int warp_m = wid >> 1, warp_n = wid & 1;
    int m0 = blockIdx.y * 64, n0 = blockIdx.x * 128;
    int K2 = K >> 1;

    int ar[4], ac[4], ap[4], br[8], bc[8], bp[8];
    #pragma unroll
    for (int i = 0; i < 4; i++){
        int w = tid + i*128; ar[i] = w >> 3; ac[i] = w & 7;
        ap[i] = ((ac[i] & 3) << 1) | (ac[i] >> 2);
    }
    #pragma unroll
    for (int i = 0; i < 8; i++){
        int w = tid + i*128; br[i] = w >> 3; bc[i] = w & 7;
        bp[i] = ((bc[i] & 3) << 1) | (bc[i] >> 2);
    }

    uint32 pah[4], pal[4], pbh[8], pbl[8];
    #pragma unroll
    for (int i = 0; i < 4; i++){
        size_t rowoff = (size_t)(m0 + ar[i]) * K2;
        pah[i] = ((const uint32*)Ah)[rowoff + ac[i]];
        pal[i] = ((const uint32*)Al)[rowoff + ac[i]];
    }
    #pragma unroll
    for (int i = 0; i < 8; i++){
        size_t rowoff = (size_t)(n0 + br[i]) * K2;
        pbh[i] = ((const uint32*)Bth)[rowoff + bc[i]];
        pbl[i] = ((const uint32*)Btl)[rowoff + bc[i]];
    }
    #pragma unroll
    for (int i = 0; i < 4; i++){ AsH[0][ar[i]][ap[i]] = pah[i]; AsL[0][ar[i]][ap[i]] = pal[i]; }
    #pragma unroll
    for (int i = 0; i < 8; i++){ BsH[0][br[i]][bp[i]] = pbh[i]; BsL[0][br[i]][bp[i]] = pbl[i]; }
    __syncthreads();

    float acc[2][8][4];
    #pragma unroll
    for (int fm = 0; fm < 2; fm++)
        #pragma unroll
        for (int fn = 0; fn < 8; fn++)
            #pragma unroll
            for (int i = 0; i < 4; i++) acc[fm][fn][i] = 0.f;

    int nk = K >> 4;
    for (int kt = 0; kt < nk; kt++){
        int cur = kt & 1, nxt = cur ^ 1;
        if (kt + 1 < nk){
            int kw = (kt + 1) * 8;
            #pragma unroll
            for (int i = 0; i < 4; i++){
                size_t rowoff = (size_t)(m0 + ar[i]) * K2 + kw;
                pah[i] = ((const uint32*)Ah)[rowoff + ac[i]];
                pal[i] = ((const uint32*)Al)[rowoff + ac[i]];
            }
            #pragma unroll
            for (int i = 0; i < 8; i++){
                size_t rowoff = (size_t)(n0 + br[i]) * K2 + kw;
                pbh[i] = ((const uint32*)Bth)[rowoff + bc[i]];
                pbl[i] = ((const uint32*)Btl)[rowoff + bc[i]];
            }
        }
        uint32 ah[2][4], al[2][4], bh[8][2], bl[8][2];
        #pragma unroll
        for (int fm = 0; fm < 2; fm++){
            int r0 = warp_m*32 + fm*16 + g;
            uint2 u0 = *(const uint2*)&AsH[cur][r0][2*t4];
            uint2 u1 = *(const uint2*)&AsH[cur][r0+8][2*t4];
            ah[fm][0] = u0.x; ah[fm][1] = u1.x; ah[fm][2] = u0.y; ah[fm][3] = u1.y;
            uint2 v0 = *(const uint2*)&AsL[cur][r0][2*t4];
            uint2 v1 = *(const uint2*)&AsL[cur][r0+8][2*t4];
            al[fm][0] = v0.x; al[fm][1] = v1.x; al[fm][2] = v0.y; al[fm][3] = v1.y;
        }
        #pragma unroll
        for (int fn = 0; fn < 8; fn++){
            int r0 = warp_n*64 + fn*8 + g;
            uint2 u = *(const uint2*)&BsH[cur][r0][2*t4];
            bh[fn][0] = u.x; bh[fn][1] = u.y;
            uint2 v = *(const uint2*)&BsL[cur][r0][2*t4];
            bl[fn][0] = v.x; bl[fn][1] = v.y;
        }
        #pragma unroll
        for (int fn = 0; fn < 8; fn++)
            #pragma unroll
            for (int fm = 0; fm < 2; fm++){
                mma16816(acc[fm][fn], ah[fm], bh[fn]);
                mma16816(acc[fm][fn], ah[fm], bl[fn]);
                mma16816(acc[fm][fn], al[fm], bh[fn]);
            }
        if (kt + 1 < nk){
            #pragma unroll
            for (int i = 0; i < 4; i++){ AsH[nxt][ar[i]][ap[i]] = pah[i]; AsL[nxt][ar[i]][ap[i]] = pal[i]; }
            #pragma unroll
            for (int i = 0; i < 8; i++){ BsH[nxt][br[i]][bp[i]] = pbh[i]; BsL[nxt][br[i]][bp[i]] = pbl[i]; }
            __syncthreads();
        }
    }

    if (MODE == 3){
        // pass 1: write x2 (bias applied), accumulate row partials
        float sums[4] = {0.f,0.f,0.f,0.f}, sqs[4] = {0.f,0.f,0.f,0.f};
        #pragma unroll
        for (int fm = 0; fm < 2; fm++){
            int m1 = m0 + warp_m*32 + fm*16 + g;
            int m2 = m1 + 8;
            #pragma unroll
            for (int fn = 0; fn < 8; fn++){
                int n = n0 + warp_n*64 + fn*8 + t4*2;
                float b0 = bias[n], b1 = bias[n+1];
                float c0 = acc[fm][fn][0] + b0;
                float c1 = acc[fm][fn][1] + b1;
                float c2 = acc[fm][fn][2] + b0;
                float c3 = acc[fm][fn][3] + b1;
                acc[fm][fn][0] = c0; acc[fm][fn][1] = c1;
                acc[fm][fn][2] = c2; acc[fm][fn][3] = c3;
                *(float2*)&C[(size_t)m1*N + n] = make_float2(c0, c1);
                *(float2*)&C[(size_t)m2*N + n] = make_float2(c2, c3);
                sums[fm*2+0] += c0 + c1; sqs[fm*2+0] += c0*c0 + c1*c1;
                sums[fm*2+1] += c2 + c3; sqs[fm*2+1] += c2*c2 + c3*c3;
            }
        }
        // quad reduce over t4 lanes (xor 1, 2)
        #pragma unroll
        for (int r = 0; r < 4; r++){
            sums[r] += __shfl_xor_sync(0xffffffffu, sums[r], 1);
            sums[r] += __shfl_xor_sync(0xffffffffu, sums[r], 2);
            sqs[r]  += __shfl_xor_sync(0xffffffffu, sqs[r], 1);
            sqs[r]  += __shfl_xor_sync(0xffffffffu, sqs[r], 2);
        }
        if (t4 == 0){
            #pragma unroll
            for (int fm = 0; fm < 2; fm++){
                int rl1 = warp_m*32 + fm*16 + g;
                sred[rl1][warp_n][0]   = sums[fm*2+0];
                sred[rl1][warp_n][1]   = sqs[fm*2+0];
                sred[rl1+8][warp_n][0] = sums[fm*2+1];
                sred[rl1+8][warp_n][1] = sqs[fm*2+1];
            }
        }
        __syncthreads();
        // pass 2: LN per row -> split bf16 xn2
        #pragma unroll
        for (int fm = 0; fm < 2; fm++){
            int rl1 = warp_m*32 + fm*16 + g;
            int m1 = m0 + rl1, m2 = m1 + 8;
            float s1 = sred[rl1][0][0]   + sred[rl1][1][0];
            float q1 = sred[rl1][0][1]   + sred[rl1][1][1];
            float s2 = sred[rl1+8][0][0] + sred[rl1+8][1][0];
            float q2 = sred[rl1+8][0][1] + sred[rl1+8][1][1];
            float mu1 = s1 * (1.0f/128.0f);
            float va1 = q1 * (1.0f/128.0f) - mu1*mu1;
            float rs1 = rsqrtf(va1 + 1e-5f);
            float mu2 = s2 * (1.0f/128.0f);
            float va2 = q2 * (1.0f/128.0f) - mu2*mu2;
            float rs2 = rsqrtf(va2 + 1e-5f);
            #pragma unroll
            for (int fn = 0; fn < 8; fn++){
                int n = n0 + warp_n*64 + fn*8 + t4*2;
                float g0 = aux1[n], g1 = aux1[n+1];
                float be0 = aux2[n], be1 = aux2[n+1];
                float o0 = (acc[fm][fn][0]-mu1)*rs1*g0 + be0;
                float o1 = (acc[fm][fn][1]-mu1)*rs1*g1 + be1;
                float o2 = (acc[fm][fn][2]-mu2)*rs2*g0 + be0;
                float o3 = (acc[fm][fn][3]-mu2)*rs2*g1 + be1;
                uint32 hp1, lp1, hp2, lp2;
                pack2_split(o0, o1, hp1, lp1);
                pack2_split(o2, o3, hp2, lp2);
                *(uint32*)&Oh[(size_t)m1*N + n] = hp1;
                *(uint32*)&Ol[(size_t)m1*N + n] = lp1;
                *(uint32*)&Oh[(size_t)m2*N + n] = hp2;
                *(uint32*)&Ol[(size_t)m2*N + n] = lp2;
            }
        }
        return;
    }

    #pragma unroll
    for (int fm = 0; fm < 2; fm++){
        int m1 = m0 + warp_m*32 + fm*16 + g;
        int m2 = m1 + 8;
        // MODE 4: per-row bilinear sample setup
        float w1c[4], w2c[4]; int l1c[4], l2c[4];
        if (MODE == 4){
            #pragma unroll
            for (int rr = 0; rr < 2; rr++){
                int m = rr ? m2 : m1;
                float px = g_posd[(size_t)m*2], py = g_posd[(size_t)m*2 + 1];
                float ix = ((px*2.f)*56.f - 1.f)*0.5f;
                float iy = ((py*2.f)*56.f - 1.f)*0.5f;
                float x0 = floorf(ix), y0 = floorf(iy);
                float wx = ix - x0, wy = iy - y0;
                #pragma unroll
                for (int cy = 0; cy < 2; cy++)
                    #pragma unroll
                    for (int cx = 0; cx < 2; cx++){
                        float xc = x0 + cx, yc = y0 + cy;
                        float wgt = (cx ? wx : 1.f-wx) * (cy ? wy : 1.f-wy);
                        bool valid = (xc >= 0.f) && (xc < 56.f) && (yc >= 0.f) && (yc < 56.f);
                        float wv = valid ? wgt : 0.f;
                        int xi = (int)fminf(fmaxf(xc, 0.f), 55.f);
                        int yi = (int)fminf(fmaxf(yc, 0.f), 55.f);
                        int idx = cy*2 + cx;
                        if (rr){ w2c[idx] = wv; l2c[idx] = yi*56 + xi; }
                        else   { w1c[idx] = wv; l1c[idx] = yi*56 + xi; }
                    }
            }
        }
        #pragma unroll
        for (int fn = 0; fn < 8; fn++){
            int n = n0 + warp_n*64 + fn*8 + t4*2;
            float b0 = (MODE != 2 && bias) ? bias[n] : 0.f;
            float b1 = (MODE != 2 && bias) ? bias[n+1] : 0.f;
            float c0 = acc[fm][fn][0] + b0;
            float c1 = acc[fm][fn][1] + b1;
            float c2 = acc[fm][fn][2] + b0;
            float c3 = acc[fm][fn][3] + b1;
            if (MODE == 0 || MODE == 4){
                if (add){
                    c0 += add[(size_t)m1*N + n];   c1 += add[(size_t)m1*N + n + 1];
                    c2 += add[(size_t)m2*N + n];   c3 += add[(size_t)m2*N + n + 1];
                }
                if (MODE == 4){
                    #pragma unroll
                    for (int cc = 0; cc < 4; cc++){
                        float2 p1 = *(const float2*)&aux1[(size_t)l1c[cc]*128 + n];
                        float2 p2 = *(const float2*)&aux1[(size_t)l2c[cc]*128 + n];
                        c0 += p1.x * w1c[cc]; c1 += p1.y * w1c[cc];
                        c2 += p2.x * w2c[cc]; c3 += p2.y * w2c[cc];
                    }
                }
                *(float2*)&C[(size_t)m1*N + n] = make_float2(c0, c1);
                *(float2*)&C[(size_t)m2*N + n] = make_float2(c2, c3);
            } else {
                if (MODE == 1){
                    c0 = 0.5f*c0*(1.0f + erff(c0*0.70710678118654752f));
                    c1 = 0.5f*c1*(1.0f + erff(c1*0.70710678118654752f));
                    c2 = 0.5f*c2*(1.0f + erff(c2*0.70710678118654752f));
                    c3 = 0.5f*c3*(1.0f + erff(c3*0.70710678118654752f));
                }
                uint32 hp1, lp1, hp2, lp2;
                pack2_split(c0, c1, hp1, lp1);
                pack2_split(c2, c3, hp2, lp2);
                *(uint32*)&Oh[(size_t)m1*N + n] = hp1;
                *(uint32*)&Ol[(size_t)m1*N + n] = lp1;
                *(uint32*)&Oh[(size_t)m2*N + n] = hp2;
                *(uint32*)&Ol[(size_t)m2*N + n] = lp2;
            }
        }
    }
}

// ---------------- tensor-core attention -------------------------------------
#define JT 224
#define KSTRIDE 34
#define VSTRIDE 114
__global__ void attn_mma_kernel(){
    extern __shared__ uint32 smu[];
    uint32* Kh  = smu;                        // [224][34]
    uint32* Kl  = Kh + JT*KSTRIDE;
    uint32* Vth = Kl + JT*KSTRIDE;            // [64][114] (V transposed)
    uint32* Vtl = Vth + 64*VSTRIDE;
    int bh = blockIdx.y;
    int b = bh >> 1, h = bh & 1;
    int tid = threadIdx.x, lane = tid & 31, w = tid >> 5;
    int g = lane >> 2, t4 = lane & 3;
    const uint32* kvh32 = (const uint32*)g_kvh;
    const uint32* kvl32 = (const uint32*)g_kvl;

    for (int e = tid; e < JT*32; e += 256){
        int j = e >> 5, p = e & 31;
        int c = p >> 3, pp = p & 7;
        int pos = c*8 + (((pp & 3) << 1) | (pp >> 2));
        uint32 vh = 0, vl = 0;
        if (j < NSR){
            size_t off = ((size_t)b*NSR + j)*128 + h*32 + p;
            vh = kvh32[off]; vl = kvl32[off];
        }
        Kh[j*KSTRIDE + pos] = vh;
        Kl[j*KSTRIDE + pos] = vl;
    }
    __nv_bfloat16* VthHW = (__nv_bfloat16*)Vth;
    __nv_bfloat16* VtlHW = (__nv_bfloat16*)Vtl;
    for (int e2 = tid; e2 < JT*32; e2 += 256){
        int j = e2 >> 5, e = e2 & 31;
        uint32 vh = 0, vl = 0;
        if (j < NSR){
            size_t off = ((size_t)b*NSR + j)*128 + 64 + h*32 + e;
            vh = kvh32[off]; vl = kvl32[off];
        }
        int pj = j >> 1, c = pj >> 3, pp = pj & 7;
        int pos = c*8 + (((pp & 3) << 1) | (pp >> 2));
        int hw = pos*2 + (j & 1);
        int d0 = 2*e;
        VthHW[(size_t)d0*(VSTRIDE*2) + hw]     = ((__nv_bfloat16*)&vh)[0];
        VthHW[(size_t)(d0+1)*(VSTRIDE*2) + hw] = ((__nv_bfloat16*)&vh)[1];
        VtlHW[(size_t)d0*(VSTRIDE*2) + hw]     = ((__nv_bfloat16*)&vl)[0];
        VtlHW[(size_t)(d0+1)*(VSTRIDE*2) + hw] = ((__nv_bfloat16*)&vl)[1];
    }

    int qr0 = blockIdx.x * 128 + w * 16;
    int gq1 = min(qr0 + g, ND - 1);
    int gq2 = min(qr0 + g + 8, ND - 1);
    size_t ro1 = ((size_t)b*ND + gq1) * 64;
    size_t ro2 = ((size_t)b*ND + gq2) * 64;
    const uint32* qh32 = (const uint32*)g_qh;
    const uint32* ql32 = (const uint32*)g_ql;
    uint32 qah[4][4], qal[4][4];
    #pragma unroll
    for (int c = 0; c < 4; c++){
        qah[c][0] = qh32[ro1 + h*32 + c*8 + t4];
        qah[c][1] = qh32[ro2 + h*32 + c*8 + t4];
        qah[c][2] = qh32[ro1 + h*32 + c*8 + 4 + t4];
        qah[c][3] = qh32[ro2 + h*32 + c*8 + 4 + t4];
        qal[c][0] = ql32[ro1 + h*32 + c*8 + t4];
        qal[c][1] = ql32[ro2 + h*32 + c*8 + t4];
        qal[c][2] = ql32[ro1 + h*32 + c*8 + 4 + t4];
        qal[c][3] = ql32[ro2 + h*32 + c*8 + 4 + t4];
    }
    __syncthreads();

    float sacc[28][4];
    #pragma unroll
    for (int fn = 0; fn < 28; fn++)
        #pragma unroll
        for (int i = 0; i < 4; i++) sacc[fn][i] = 0.f;
    #pragma unroll
    for (int c = 0; c < 4; c++)
        #pragma unroll
        for (int fn = 0; fn < 28; fn++){
            int r0 = fn*8 + g;
            uint2 uh = *(const uint2*)&Kh[r0*KSTRIDE + c*8 + 2*t4];
            uint2 ul = *(const uint2*)&Kl[r0*KSTRIDE + c*8 + 2*t4];
            uint32 bhf[2] = {uh.x, uh.y}, blf[2] = {ul.x, ul.y};
            mma16816(sacc[fn], qah[c], bhf);
            mma16816(sacc[fn], qah[c], blf);
            mma16816(sacc[fn], qal[c], bhf);
        }

    const float scale = 0.17677669529663687f;   // 32^-0.5
    float mx0 = -1e30f, mx1 = -1e30f;
    #pragma unroll
    for (int fn = 0; fn < 28; fn++){
        int jb = fn*8 + t4*2;
        #pragma unroll
        for (int i = 0; i < 4; i++){
            int j = jb + (i & 1);
            float s = sacc[fn][i] * scale;
            s = (j < NSR) ? s : -1e30f;
            sacc[fn][i] = s;
            if (i < 2) mx0 = fmaxf(mx0, s); else mx1 = fmaxf(mx1, s);
        }
    }
    mx0 = fmaxf(mx0, __shfl_xor_sync(0xffffffffu, mx0, 1));
    mx0 = fmaxf(mx0, __shfl_xor_sync(0xffffffffu, mx0, 2));
    mx1 = fmaxf(mx1, __shfl_xor_sync(0xffffffffu, mx1, 1));
    mx1 = fmaxf(mx1, __shfl_xor_sync(0xffffffffu, mx1, 2));
    float sum0 = 0.f, sum1 = 0.f;
    #pragma unroll
    for (int fn = 0; fn < 28; fn++){
        #pragma unroll
        for (int i = 0; i < 4; i++){
            float p = expf(sacc[fn][i] - ((i < 2) ? mx0 : mx1));
            sacc[fn][i] = p;
            if (i < 2) sum0 += p; else sum1 += p;
        }
    }
    sum0 += __shfl_xor_sync(0xffffffffu, sum0, 1);
    sum0 += __shfl_xor_sync(0xffffffffu, sum0, 2);
    sum1 += __shfl_xor_sync(0xffffffffu, sum1, 1);
    sum1 += __shfl_xor_sync(0xffffffffu, sum1, 2);

    float oacc[8][4];
    #pragma unroll
    for (int fn = 0; fn < 8; fn++)
        #pragma unroll
        for (int i = 0; i < 4; i++) oacc[fn][i] = 0.f;
    #pragma unroll
    for (int kc = 0; kc < 14; kc++){
        uint32 ph[4], pl[4];
        pack2_split(sacc[2*kc][0],   sacc[2*kc][1],   ph[0], pl[0]);
        pack2_split(sacc[2*kc][2],   sacc[2*kc][3],   ph[1], pl[1]);
        pack2_split(sacc[2*kc+1][0], sacc[2*kc+1][1], ph[2], pl[2]);
        pack2_split(sacc[2*kc+1][2], sacc[2*kc+1][3], ph[3], pl[3]);
        #pragma unroll
        for (int fn = 0; fn < 8; fn++){
            int r0 = fn*8 + g;
            uint2 uh = *(const uint2*)&Vth[r0*VSTRIDE + kc*8 + 2*t4];
            uint2 ul = *(const uint2*)&Vtl[r0*VSTRIDE + kc*8 + 2*t4];
            uint32 bhf[2] = {uh.x, uh.y}, blf[2] = {ul.x, ul.y};
            mma16816(oacc[fn], ph, bhf);
            mma16816(oacc[fn], ph, blf);
            mma16816(oacc[fn], pl, bhf);
        }
    }

    float inv0 = 1.0f / sum0, inv1 = 1.0f / sum1;
    int q1 = qr0 + g, q2 = qr0 + g + 8;
    #pragma unroll
    for (int fn = 0; fn < 8; fn++){
        int d = fn*8 + t4*2;
        if (q1 < ND){
            size_t cb = ((size_t)b*ND + q1)*KCAT + h*64 + d;
            uint32 hp, lp;
            pack2_split(oacc[fn][0]*inv0, oacc[fn][1]*inv0, hp, lp);
            *(uint32*)&g_cath[cb] = hp;
            *(uint32*)&g_catl[cb] = lp;
        }
        if (q2 < ND){
            size_t cb = ((size_t)b*ND + q2)*KCAT + h*64 + d;
            uint32 hp, lp;
            pack2_split(oacc[fn][2]*inv1, oacc[fn][3]*inv1, hp, lp);
            *(uint32*)&g_cath[cb] = hp;
            *(uint32*)&g_catl[cb] = lp;
        }
    }
}

// ---------------- launcher ---------------------------------------------------
extern "C" void kernel_launch(void* const* d_in, const int* in_sizes, int n_in,
                              void* d_out, int out_size){
    const float* x        = (const float*)d_in[0];
    const float* pos      = (const float*)d_in[1];
    const float* pos_embed= (const float*)d_in[2];
    const float* noise_u  = (const float*)d_in[3];
    const float* norm_g   = (const float*)d_in[4];
    const float* norm_b   = (const float*)d_in[5];
    const float* conf_w   = (const float*)d_in[6];
    const float* conf_b   = (const float*)d_in[7];
    const float* n1g      = (const float*)d_in[8];
    const float* n1b      = (const float*)d_in[9];
    const float* q_w      = (const float*)d_in[10];
    const float* k_w      = (const float*)d_in[11];
    const float* v_w      = (const float*)d_in[12];
    const float* proj_w   = (const float*)d_in[13];
    const float* proj_b   = (const float*)d_in[14];
    const float* sr_w     = (const float*)d_in[15];
    const float* sr_b     = (const float*)d_in[16];
    const float* srn_g    = (const float*)d_in[17];
    const float* srn_b    = (const float*)d_in[18];
    const float* fc_w     = (const float*)d_in[19];
    const float* fc_b     = (const float*)d_in[20];
    const float* n2g      = (const float*)d_in[21];
    const float* n2b      = (const float*)d_in[22];
    const float* fc1_w    = (const float*)d_in[23];
    const float* fc1_b    = (const float*)d_in[24];
    const float* fc2_w    = (const float*)d_in[25];
    const float* fc2_b    = (const float*)d_in[26];
    float* out = (float*)d_out;

    float *p_xs, *p_x2, *p_biaspf;
    __nv_bfloat16 *p_xnh, *p_xnl, *p_xsh, *p_xsl, *p_cath, *p_catl;
    __nv_bfloat16 *p_qh, *p_ql, *p_kvh, *p_kvl;
    __nv_bfloat16 *p_xn2h, *p_xn2l, *p_hidh, *p_hidl;
    __nv_bfloat16 *p_w1h, *p_w1l, *p_w2h, *p_w2l, *p_wqh, *p_wql, *p_wkvh, *p_wkvl, *p_wpfh, *p_wpfl;
    cudaGetSymbolAddress((void**)&p_xs,    g_xs);
    cudaGetSymbolAddress((void**)&p_x2,    g_x2);
    cudaGetSymbolAddress((void**)&p_biaspf,g_biaspf);
    cudaGetSymbolAddress((void**)&p_xnh,   g_xnh);
    cudaGetSymbolAddress((void**)&p_xnl,   g_xnl);
    cudaGetSymbolAddress((void**)&p_xsh,   g_xsh);
    cudaGetSymbolAddress((void**)&p_xsl,   g_xsl);
    cudaGetSymbolAddress((void**)&p_qh,    g_qh);
    cudaGetSymbolAddress((void**)&p_ql,    g_ql);
    cudaGetSymbolAddress((void**)&p_kvh,   g_kvh);
    cudaGetSymbolAddress((void**)&p_kvl,   g_kvl);
    cudaGetSymbolAddress((void**)&p_cath,  g_cath);
    cudaGetSymbolAddress((void**)&p_catl,  g_catl);
    cudaGetSymbolAddress((void**)&p_xn2h,  g_xn2h);
    cudaGetSymbolAddress((void**)&p_xn2l,  g_xn2l);
    cudaGetSymbolAddress((void**)&p_hidh,  g_hidh);
    cudaGetSymbolAddress((void**)&p_hidl,  g_hidl);
    cudaGetSymbolAddress((void**)&p_w1h,   g_w1h);
    cudaGetSymbolAddress((void**)&p_w1l,   g_w1l);
    cudaGetSymbolAddress((void**)&p_w2h,   g_w2h);
    cudaGetSymbolAddress((void**)&p_w2l,   g_w2l);
    cudaGetSymbolAddress((void**)&p_wqh,   g_wqh);
    cudaGetSymbolAddress((void**)&p_wql,   g_wql);
    cudaGetSymbolAddress((void**)&p_wkvh,  g_wkvh);
    cudaGetSymbolAddress((void**)&p_wkvl,  g_wkvl);
    cudaGetSymbolAddress((void**)&p_wpfh,  g_wpfh);
    cudaGetSymbolAddress((void**)&p_wpfl,  g_wpfl);

    zero_kernel<<<4096, 256>>>();
    prep_kernel<<<(180288 + 255)/256, 256>>>(fc1_w, fc2_w, q_w, k_w, v_w, proj_w, fc_w, proj_b, fc_b);

    // fused LN+scatter+score (coalesced smem staging)
    size_t ls_smem = (256*64 + 512) * sizeof(float);
    cudaFuncSetAttribute(lnscore_kernel, cudaFuncAttributeMaxDynamicSharedMemorySize, (int)ls_smem);
    lnscore_kernel<<<Bv*Nv/256, 256, ls_smem>>>(x, pos, noise_u, n1g, n1b, norm_g, norm_b, conf_w, conf_b);

    topk_kernel<<<Bv, 1024>>>();
    gather_ln_kernel<<<(Bv*ND + 7)/8, 256>>>(x, pos, n1g, n1b);
    blur_kernel<<<(Bv*Nv*Cv + 255)/256, 256>>>();
    srconv_kernel<<<196, 256>>>(sr_w, sr_b);
    ln64_split_kernel<<<(MSR + 7)/8, 256>>>(p_xs, p_xsh, p_xsl, srn_g, srn_b, MSR);

    // q = xn @ q_w ; [k|v] = xs @ [k_w|v_w]   -> split bf16 outputs
    mma_gemm_kernel<2><<<dim3(1, MROWS/64), 128>>>(
        p_xnh, p_xnl, p_wqh, p_wql, nullptr, nullptr, nullptr, p_qh, p_ql,
        nullptr, nullptr, MROWS, 128, 64);
    mma_gemm_kernel<2><<<dim3(2, MSR/64), 128>>>(
        p_xsh, p_xsl, p_wkvh, p_wkvl, nullptr, nullptr, nullptr, p_kvh, p_kvl,
        nullptr, nullptr, MSR, 256, 64);

    // tensor-core attention -> concat buffer cols [0:128)
    size_t attn_smem = (size_t)(JT*KSTRIDE*2 + 64*VSTRIDE*2) * sizeof(uint32);
    cudaFuncSetAttribute(attn_mma_kernel, cudaFuncAttributeMaxDynamicSharedMemorySize, (int)attn_smem);
    attn_mma_kernel<<<dim3(7, Bv*2), 256, attn_smem>>>();

    // x2 = [oatt|xdown] @ [proj_w;fc_w] + biaspf ; fused LN2 -> xn2 split
    mma_gemm_kernel<3><<<dim3(1, MROWS/64), 128>>>(
        p_cath, p_catl, p_wpfh, p_wpfl, p_biaspf, nullptr, p_x2, p_xn2h, p_xn2l,
        n2g, n2b, MROWS, 128, KCAT);

    // hid = gelu(xn2 @ fc1 + b1) -> split bf16 (tensor cores)
    mma_gemm_kernel<1><<<dim3(HIDN/128, MROWS/64), 128>>>(
        p_xn2h, p_xn2l, p_w1h, p_w1l, fc1_b, nullptr, nullptr, p_hidh, p_hidl,
        nullptr, nullptr, MROWS, HIDN, DOUT);
    // out = x2 + hid @ fc2 + b2 + grid_sample(pos_embed)  (fused epilogue)
    mma_gemm_kernel<4><<<dim3(DOUT/128, MROWS/64), 128>>>(
        p_hidh, p_hidl, p_w2h, p_w2l, fc2_b, p_x2, out, nullptr, nullptr,
        pos_embed, nullptr, MROWS, DOUT, HIDN);
}